// round 12
// baseline (speedup 1.0000x reference)
#include <cuda_runtime.h>
#include <cuda_fp16.h>
#include <math.h>
#include <stdint.h>

#define NN     3072
#define EE     98304
#define FDIM   1024
#define HD     64
#define MAXDEG 256
#define KP     1024          // fp16 GEMM K
#define NTP    (KP / 32)     // 32 BK32 tiles
#define WPSZ   ((size_t)FDIM * KP)

// ---------------- scratch (static device arrays; no allocation) ----------------
__device__ int   g_cnt[NN];                   // zero-init; csr2 resets after use
__device__ int   g_ecol[NN * MAXDEG];
__device__ int   g_eeid[NN * MAXDEG];
__device__ int   g_adj[NN * MAXDEG];
__device__ int   g_deg[NN];
__device__ __half g_q2h[NN * FDIM];           // fp16 q2/k2/v2
__device__ __half g_k2h[NN * FDIM];
__device__ __half g_v2h[NN * FDIM];
__device__ float g_bf[3 * FDIM];              // fused biases
__device__ float g_zb[FDIM];                  // zero bias (static zero-init)
__device__ __half g_ab   [NN * KP];           // fp16 cast of x
__device__ __half g_abatt[NN * KP];           // fp16 cast of attn out
__device__ __half g_wia[3 * WPSZ];            // fp16 cast of Wiq/Wik/Wiv
__device__ __half g_wtb[3 * WPSZ];            // fp16 cast of Wq^T/Wk^T/Wv^T
__device__ __half g_wb [4 * WPSZ];            // fp16: Wf0..2 (from fuse), wo

// ---------------- PTX helpers ----------------
__device__ __forceinline__ uint32_t smem_u32(const void* p) {
    uint32_t a;
    asm("{ .reg .u64 t; cvta.to.shared.u64 t, %1; cvt.u32.u64 %0, t; }" : "=r"(a) : "l"(p));
    return a;
}
__device__ __forceinline__ void cp16(uint32_t dst, const void* src) {
    asm volatile("cp.async.cg.shared.global [%0], [%1], 16;" :: "r"(dst), "l"(src));
}
__device__ __forceinline__ void ldsm4(uint32_t* r, uint32_t a) {
    asm volatile("ldmatrix.sync.aligned.m8n8.x4.shared.b16 {%0,%1,%2,%3}, [%4];"
                 : "=r"(r[0]), "=r"(r[1]), "=r"(r[2]), "=r"(r[3]) : "r"(a));
}
__device__ __forceinline__ void ldsm2(uint32_t* r, uint32_t a) {
    asm volatile("ldmatrix.sync.aligned.m8n8.x2.shared.b16 {%0,%1}, [%2];"
                 : "=r"(r[0]), "=r"(r[1]) : "r"(a));
}
__device__ __forceinline__ void mma16816(float* c, const uint32_t* a, const uint32_t* b) {
    asm volatile(
        "mma.sync.aligned.m16n8k16.row.col.f32.f16.f16.f32 "
        "{%0,%1,%2,%3}, {%4,%5,%6,%7}, {%8,%9}, {%0,%1,%2,%3};"
        : "+f"(c[0]), "+f"(c[1]), "+f"(c[2]), "+f"(c[3])
        : "r"(a[0]), "r"(a[1]), "r"(a[2]), "r"(a[3]), "r"(b[0]), "r"(b[1]));
}

// ---------------- phase 1: all independent prep work in ONE launch ----------------
#define P1_BLOCKS 10636

struct ProArgs {
    const float *x;
    const int   *ei, *et;
    const float *wq, *wk, *wv, *wiq, *wik, *wiv, *wo;
    const float *bq, *bk, *bv, *biq, *bik, *biv;
};

__global__ __launch_bounds__(256) void prologue_kernel(ProArgs a) {
    const int b   = blockIdx.x;
    const int tid = threadIdx.x;

    if (b < 3072) {                                   // ---- conv_wia ----
        const int w  = b >> 10;
        const int i  = (b & 1023) * 256 + tid;
        const float* W = (w == 0) ? a.wiq : (w == 1) ? a.wik : a.wiv;
        float4 v = ((const float4*)W)[i];
        __half2 h01, h23;
        h01.x = __float2half_rn(v.x); h01.y = __float2half_rn(v.y);
        h23.x = __float2half_rn(v.z); h23.y = __float2half_rn(v.w);
        __half* A = g_wia + (size_t)w * WPSZ;
        *(__half2*)(A + i * 4)     = h01;
        *(__half2*)(A + i * 4 + 2) = h23;
    } else if (b < 6144) {                            // ---- conv_wt ----
        const int bb = b - 3072;
        const int w  = bb >> 10;
        const int t2 = bb & 1023;
        const int n0 = (t2 & 31) * 32;
        const int k0 = (t2 >> 5) * 32;
        const float* W = (w == 0) ? a.wq : (w == 1) ? a.wk : a.wv;
        __shared__ float t[32][33];
        const int tx = tid & 31;
        const int ty = tid >> 5;
        #pragma unroll
        for (int r = ty; r < 32; r += 8)
            t[r][tx] = W[(size_t)(k0 + r) * FDIM + n0 + tx];
        __syncthreads();
        __half* B = g_wtb + (size_t)w * WPSZ;
        #pragma unroll
        for (int rr = ty; rr < 32; rr += 8)
            B[(size_t)(n0 + rr) * KP + k0 + tx] = __float2half_rn(t[tx][rr]);
    } else if (b < 7168) {                            // ---- wo cast ----
        const int i = (b - 6144) * 256 + tid;
        float4 v = ((const float4*)a.wo)[i];
        __half2 h01, h23;
        h01.x = __float2half_rn(v.x); h01.y = __float2half_rn(v.y);
        h23.x = __float2half_rn(v.z); h23.y = __float2half_rn(v.w);
        __half* A = g_wb + (size_t)3 * WPSZ;
        *(__half2*)(A + i * 4)     = h01;
        *(__half2*)(A + i * 4 + 2) = h23;
    } else if (b < 10240) {                           // ---- x cast ----
        const int i = (b - 7168) * 256 + tid;
        float4 v = ((const float4*)a.x)[i];
        __half2 h01, h23;
        h01.x = __float2half_rn(v.x); h01.y = __float2half_rn(v.y);
        h23.x = __float2half_rn(v.z); h23.y = __float2half_rn(v.w);
        *(__half2*)(g_ab + i * 4)     = h01;
        *(__half2*)(g_ab + i * 4 + 2) = h23;
    } else if (b < 10624) {                           // ---- edge scatter ----
        const int e = (b - 10240) * 256 + tid;
        int s = a.ei[e], d = a.ei[EE + e];
        int pos = atomicAdd(&g_cnt[s], 1);
        if (pos < MAXDEG) {
            g_ecol[s * MAXDEG + pos] = d | (a.et[e] << 20);
            g_eeid[s * MAXDEG + pos] = e;
        }
    } else {                                          // ---- bias fuse ----
        const int idx = b - 10624;
        const int z   = idx >> 2;
        const int n   = (idx & 3) * 256 + tid;
        const float* W  = ((z == 0) ? a.wiq : (z == 1) ? a.wik : a.wiv) + (size_t)n * FDIM;
        const float* bi = (z == 0) ? a.bq : (z == 1) ? a.bk : a.bv;
        const float* bo = (z == 0) ? a.biq : (z == 1) ? a.bik : a.biv;
        float s = 0.f;
        #pragma unroll 8
        for (int k = 0; k < FDIM; k++) s = fmaf(W[k], bi[k], s);
        g_bf[z * FDIM + n] = s + bo[n];
    }
}

// ---------------- mma.sync fp16 GEMM core ----------------
#define STAGE_BYTES 16384
#define GEMM_SMEM   (3 * STAGE_BYTES)

__device__ __forceinline__ void load_tile_pair(
    const __half* Abase, const __half* Bbase,
    int row0, int col0, int k0, uint32_t sA, uint32_t sB, int tid)
{
    #pragma unroll
    for (int i = 0; i < 2; i++) {
        int c   = tid + i * 256;
        int row = c >> 2;
        int kc  = c & 3;
        uint32_t soff = (uint32_t)(((row >> 3) * 4 + kc) * 128 + (row & 7) * 16);
        cp16(sA + soff, Abase + (size_t)(row0 + row) * KP + k0 + kc * 8);
        cp16(sB + soff, Bbase + (size_t)(col0 + row) * KP + k0 + kc * 8);
    }
}

// MODE 0: fp32 out + bias.  MODE 1: fp16 out + bias.  Row stride FDIM both.
template<int MODE>
__device__ __forceinline__ void gemm_core(
    int bx, int by,
    const __half* __restrict__ A, const __half* __restrict__ B,
    const float* __restrict__ bias, float* __restrict__ Yf,
    __half* __restrict__ Ys)
{
    extern __shared__ char smem[];
    const uint32_t sb = smem_u32(smem);
    const int tid  = threadIdx.x;
    const int wid  = tid >> 5;
    const int lane = tid & 31;
    const int wm   = wid & 1;
    const int wn   = wid >> 1;
    const int row0 = by << 7;
    const int col0 = bx << 7;

    const int g  = lane >> 3;
    const int r8 = lane & 7;
    const uint32_t aconst = (uint32_t)((wm * 8 + (g & 1)) * 512 + (g >> 1) * 128 + r8 * 16);
    const uint32_t bconst = (uint32_t)(wn * 4 * 512 + (g & 1) * 128 + r8 * 16);

    float acc[4][4][4];
    #pragma unroll
    for (int mt = 0; mt < 4; mt++)
        #pragma unroll
        for (int nt = 0; nt < 4; nt++)
            acc[mt][nt][0] = acc[mt][nt][1] = acc[mt][nt][2] = acc[mt][nt][3] = 0.f;

    load_tile_pair(A, B, row0, col0, 0, sb, sb + 8192, tid);
    asm volatile("cp.async.commit_group;" ::: "memory");
    load_tile_pair(A, B, row0, col0, 32, sb + STAGE_BYTES, sb + STAGE_BYTES + 8192, tid);
    asm volatile("cp.async.commit_group;" ::: "memory");

    int buf = 0;
    for (int t = 0; t < NTP; t++) {
        asm volatile("cp.async.wait_group 1;" ::: "memory");
        __syncthreads();

        int nbuf = buf + 1; if (nbuf == 3) nbuf = 0;
        int lbuf = nbuf + 1; if (lbuf == 3) lbuf = 0;
        if (t + 2 < NTP) {
            uint32_t ls = sb + (uint32_t)lbuf * STAGE_BYTES;
            load_tile_pair(A, B, row0, col0, (t + 2) * 32, ls, ls + 8192, tid);
        }
        asm volatile("cp.async.commit_group;" ::: "memory");

        const uint32_t Ab = sb + (uint32_t)buf * STAGE_BYTES;
        const uint32_t Bb = Ab + 8192;
        #pragma unroll
        for (int kt = 0; kt < 2; kt++) {
            uint32_t af[4][4], bfr[4][2];
            #pragma unroll
            for (int mt = 0; mt < 4; mt++)
                ldsm4(af[mt], Ab + aconst + (uint32_t)(mt * 1024 + kt * 256));
            #pragma unroll
            for (int nt = 0; nt < 4; nt++)
                ldsm2(bfr[nt], Bb + bconst + (uint32_t)(nt * 512 + kt * 256));
            #pragma unroll
            for (int mt = 0; mt < 4; mt++)
                #pragma unroll
                for (int nt = 0; nt < 4; nt++)
                    mma16816(acc[mt][nt], af[mt], bfr[nt]);
        }
        buf = nbuf;
    }

    const int mbase = row0 + wm * 64 + (lane >> 2);
    const int nbase = col0 + wn * 32 + (lane & 3) * 2;
    #pragma unroll
    for (int mt = 0; mt < 4; mt++) {
        #pragma unroll
        for (int nt = 0; nt < 4; nt++) {
            int m = mbase + mt * 16;
            int n = nbase + nt * 8;
            float2 b2 = *(const float2*)&bias[n];
            float y0 = acc[mt][nt][0] + b2.x, y1 = acc[mt][nt][1] + b2.y;
            float y2 = acc[mt][nt][2] + b2.x, y3 = acc[mt][nt][3] + b2.y;
            if (MODE == 0) {
                *(float2*)&Yf[(size_t)m * FDIM + n]       = make_float2(y0, y1);
                *(float2*)&Yf[(size_t)(m + 8) * FDIM + n] = make_float2(y2, y3);
            } else {
                __half2 h0, h1;
                h0.x = __float2half_rn(y0); h0.y = __float2half_rn(y1);
                h1.x = __float2half_rn(y2); h1.y = __float2half_rn(y3);
                *(__half2*)(Ys + (size_t)m * FDIM + n)       = h0;
                *(__half2*)(Ys + (size_t)(m + 8) * FDIM + n) = h1;
            }
        }
    }
}

// ---------------- phase 2: fuse GEMM (blocks 0..191) + csr dedup (192..3263) ----------------
#define P2_BLOCKS (192 + NN)

__global__ __launch_bounds__(256) void phase2_kernel() {
    if (blockIdx.x < 192) {
        const int b  = blockIdx.x;
        const int z  = b >> 6;
        const int bb = b & 63;
        gemm_core<1>(bb & 7, bb >> 3,
                     g_wia + (size_t)z * WPSZ, g_wtb + (size_t)z * WPSZ,
                     g_zb, nullptr, g_wb + (size_t)z * WPSZ);
        return;
    }
    const int n   = blockIdx.x - 192;
    const int tid = threadIdx.x;
    __shared__ int scol[MAXDEG], seid[MAXDEG];
    __shared__ int outc, sflag;
    if (tid == 0) { outc = 0; sflag = 0; }
    int cnt = g_cnt[n];
    if (cnt > MAXDEG) cnt = MAXDEG;
    if (tid < cnt) {
        scol[tid] = g_ecol[n * MAXDEG + tid];
        seid[tid] = g_eeid[n * MAXDEG + tid];
    }
    __syncthreads();
    if (tid < cnt) {
        int cj = scol[tid] & 0xFFFFF;
        int ej = seid[tid];
        bool win = true;
        for (int i = 0; i < cnt; i++)
            if ((scol[i] & 0xFFFFF) == cj && seid[i] > ej) { win = false; break; }
        if (win) {
            int pos = atomicAdd(&outc, 1);
            g_adj[n * MAXDEG + pos] = scol[tid];
            if (cj == n) sflag = 1;
        }
    }
    __syncthreads();
    if (tid == 0) {
        int d = outc;
        if (!sflag && d < MAXDEG) { g_adj[n * MAXDEG + d] = n | (4 << 20); d++; }
        g_deg[n] = d;
        g_cnt[n] = 0;           // reset for next graph replay (deterministic)
    }
}

// ---------------- phase 3: q2/k2/v2 (all fp16 out) ----------------
__global__ __launch_bounds__(256) void gemm_main_kernel() {
    const int z = blockIdx.z;
    __half* Ys = (z == 0) ? g_q2h : (z == 1) ? g_k2h : g_v2h;
    gemm_core<1>(blockIdx.x, blockIdx.y, g_ab, g_wb + (size_t)z * WPSZ,
                 g_bf + z * FDIM, nullptr, Ys);
}

// ---------------- phase 5: out = fl16(att) @ wo + bo ----------------
__global__ __launch_bounds__(256) void gemm_final_kernel(const float* bias, float* Y) {
    gemm_core<0>(blockIdx.x, blockIdx.y, g_abatt, g_wb + (size_t)3 * WPSZ, bias, Y, nullptr);
}

// ---------------- phase 4: sparse gather attention (fp16 Q/K/V, 2 CTAs/SM) ------
__global__ __launch_bounds__(512, 2) void attn_sparse_kernel(const float* __restrict__ etw)
{
    __shared__ __half q_s[FDIM];           // 2 KB
    __shared__ int    nbr_s[MAXDEG];
    __shared__ float  sc_s[16][MAXDEG];    // 16 KB
    __shared__ float  wsh_s[8];

    const int n    = blockIdx.x;
    const int tid  = threadIdx.x;
    const int hh   = tid >> 5;
    const int lane = tid & 31;

    if (tid < 4) wsh_s[tid + 1] = log1pf(expf(etw[tid]));
    ((uint32_t*)q_s)[tid] = ((const uint32_t*)(g_q2h + (size_t)n * FDIM))[tid];
    const int deg = g_deg[n];
    for (int j = tid; j < deg; j += 512) nbr_s[j] = g_adj[n * MAXDEG + j];
    __syncthreads();

    // this head's q slice: 64 halfs = 8 x uint4 = 32 regs
    uint4 qh[8];
    #pragma unroll
    for (int i = 0; i < 8; i++) qh[i] = *(const uint4*)&q_s[hh * HD + i * 8];

    float mx = -1e30f;
    for (int base = 0; base < deg; base += 32) {
        int   j = base + lane;
        float s = -1e30f;
        if (j < deg) {
            int pk   = nbr_s[j];
            int m    = pk & 0xFFFFF;
            int code = pk >> 20;
            const uint4* kp = (const uint4*)(g_k2h + (size_t)m * FDIM + hh * HD);
            float a0 = 0.f, a1 = 0.f;
            #pragma unroll
            for (int i = 0; i < 8; i += 2) {
                uint4 ka = kp[i], kb = kp[i + 1];
                uint4 qa = qh[i], qb = qh[i + 1];
                float2 k0 = __half22float2(*(__half2*)&ka.x);
                float2 k1 = __half22float2(*(__half2*)&ka.y);
                float2 k2 = __half22float2(*(__half2*)&ka.z);
                float2 k3 = __half22float2(*(__half2*)&ka.w);
                float2 q0 = __half22float2(*(__half2*)&qa.x);
                float2 q1 = __half22float2(*(__half2*)&qa.y);
                float2 q2 = __half22float2(*(__half2*)&qa.z);
                float2 q3 = __half22float2(*(__half2*)&qa.w);
                a0 = fmaf(q0.x, k0.x, a0); a0 = fmaf(q0.y, k0.y, a0);
                a0 = fmaf(q1.x, k1.x, a0); a0 = fmaf(q1.y, k1.y, a0);
                a0 = fmaf(q2.x, k2.x, a0); a0 = fmaf(q2.y, k2.y, a0);
                a0 = fmaf(q3.x, k3.x, a0); a0 = fmaf(q3.y, k3.y, a0);
                float2 g0 = __half22float2(*(__half2*)&kb.x);
                float2 g1 = __half22float2(*(__half2*)&kb.y);
                float2 g2 = __half22float2(*(__half2*)&kb.z);
                float2 g3 = __half22float2(*(__half2*)&kb.w);
                float2 p0 = __half22float2(*(__half2*)&qb.x);
                float2 p1 = __half22float2(*(__half2*)&qb.y);
                float2 p2 = __half22float2(*(__half2*)&qb.z);
                float2 p3 = __half22float2(*(__half2*)&qb.w);
                a1 = fmaf(p0.x, g0.x, a1); a1 = fmaf(p0.y, g0.y, a1);
                a1 = fmaf(p1.x, g1.x, a1); a1 = fmaf(p1.y, g1.y, a1);
                a1 = fmaf(p2.x, g2.x, a1); a1 = fmaf(p2.y, g2.y, a1);
                a1 = fmaf(p3.x, g3.x, a1); a1 = fmaf(p3.y, g3.y, a1);
            }
            s = fmaf(a0 + a1, 0.125f, wsh_s[code]);
            sc_s[hh][j] = s;
        }
        mx = fmaxf(mx, s);
    }
    #pragma unroll
    for (int off = 16; off; off >>= 1)
        mx = fmaxf(mx, __shfl_xor_sync(0xffffffffu, mx, off));
    __syncwarp();

    float sum = 0.f;
    for (int j = lane; j < deg; j += 32) {
        float p = __expf(sc_s[hh][j] - mx);
        sc_s[hh][j] = p;
        sum += p;
    }
    #pragma unroll
    for (int off = 16; off; off >>= 1)
        sum += __shfl_xor_sync(0xffffffffu, sum, off);
    const float inv = 1.f / sum;
    __syncwarp();

    const int dof = hh * HD + lane * 2;
    float o0 = 0.f, o1 = 0.f;
    #pragma unroll 4
    for (int j = 0; j < deg; j++) {
        int   m = nbr_s[j] & 0xFFFFF;
        float p = sc_s[hh][j];
        float2 f = __half22float2(*(const __half2*)(g_v2h + (size_t)m * FDIM + dof));
        o0 = fmaf(p, f.x, o0);
        o1 = fmaf(p, f.y, o1);
    }
    __half2 h;
    h.x = __float2half_rn(o0 * inv);
    h.y = __float2half_rn(o1 * inv);
    *(__half2*)(g_abatt + (size_t)n * KP + dof) = h;
}

// ---------------- launch ----------------
extern "C" void kernel_launch(void* const* d_in, const int* in_sizes, int n_in,
                              void* d_out, int out_size) {
    ProArgs a;
    a.x   = (const float*)d_in[0];
    a.ei  = (const int*)d_in[1];
    a.et  = (const int*)d_in[2];
    const float* etw = (const float*)d_in[3];
    a.wq  = (const float*)d_in[4];   a.bq  = (const float*)d_in[5];
    a.wk  = (const float*)d_in[6];   a.bk  = (const float*)d_in[7];
    a.wv  = (const float*)d_in[8];   a.bv  = (const float*)d_in[9];
    a.wiq = (const float*)d_in[10];  a.biq = (const float*)d_in[11];
    a.wik = (const float*)d_in[12];  a.bik = (const float*)d_in[13];
    a.wiv = (const float*)d_in[14];  a.biv = (const float*)d_in[15];
    a.wo  = (const float*)d_in[16];
    const float* bo = (const float*)d_in[17];
    float* out = (float*)d_out;

    cudaFuncSetAttribute(phase2_kernel,     cudaFuncAttributeMaxDynamicSharedMemorySize, GEMM_SMEM);
    cudaFuncSetAttribute(gemm_main_kernel,  cudaFuncAttributeMaxDynamicSharedMemorySize, GEMM_SMEM);
    cudaFuncSetAttribute(gemm_final_kernel, cudaFuncAttributeMaxDynamicSharedMemorySize, GEMM_SMEM);

    prologue_kernel<<<P1_BLOCKS, 256>>>(a);
    phase2_kernel<<<P2_BLOCKS, 256, GEMM_SMEM>>>();
    gemm_main_kernel<<<dim3(FDIM / 128, NN / 128, 3), 256, GEMM_SMEM>>>();
    attn_sparse_kernel<<<NN, 512>>>(etw);
    gemm_final_kernel<<<dim3(FDIM / 128, NN / 128), 256, GEMM_SMEM>>>(bo, out);
}

// round 13
// speedup vs baseline: 1.3094x; 1.3094x over previous
#include <cuda_runtime.h>
#include <cuda_fp16.h>
#include <math.h>
#include <stdint.h>

#define NN     3072
#define EE     98304
#define FDIM   1024
#define HD     64
#define MAXDEG 256
#define KP     1024          // fp16 GEMM K
#define NTP    (KP / 32)     // 32 BK32 tiles
#define WPSZ   ((size_t)FDIM * KP)

// ---------------- scratch (static device arrays; no allocation) ----------------
__device__ int   g_cnt[NN];                   // zero-init; csr2 resets after use
__device__ int   g_ecol[NN * MAXDEG];
__device__ int   g_eeid[NN * MAXDEG];
__device__ int   g_adj[NN * MAXDEG];
__device__ int   g_deg[NN];
__device__ __half g_q2h[NN * FDIM];           // fp16 q2/k2/v2
__device__ __half g_k2h[NN * FDIM];
__device__ __half g_v2h[NN * FDIM];
__device__ float g_bf[3 * FDIM];              // fused biases
__device__ float g_zb[FDIM];                  // zero bias (static zero-init)
__device__ __half g_ab   [NN * KP];           // fp16 cast of x
__device__ __half g_abatt[NN * KP];           // fp16 cast of attn out
__device__ __half g_wia[3 * WPSZ];            // fp16 cast of Wiq/Wik/Wiv
__device__ __half g_wtb[3 * WPSZ];            // fp16 cast of Wq^T/Wk^T/Wv^T
__device__ __half g_wb [4 * WPSZ];            // fp16: Wf0..2 (from fuse), wo

// ---------------- PTX helpers ----------------
__device__ __forceinline__ uint32_t smem_u32(const void* p) {
    uint32_t a;
    asm("{ .reg .u64 t; cvta.to.shared.u64 t, %1; cvt.u32.u64 %0, t; }" : "=r"(a) : "l"(p));
    return a;
}
__device__ __forceinline__ void cp16(uint32_t dst, const void* src) {
    asm volatile("cp.async.cg.shared.global [%0], [%1], 16;" :: "r"(dst), "l"(src));
}
__device__ __forceinline__ void ldsm4(uint32_t* r, uint32_t a) {
    asm volatile("ldmatrix.sync.aligned.m8n8.x4.shared.b16 {%0,%1,%2,%3}, [%4];"
                 : "=r"(r[0]), "=r"(r[1]), "=r"(r[2]), "=r"(r[3]) : "r"(a));
}
__device__ __forceinline__ void ldsm2(uint32_t* r, uint32_t a) {
    asm volatile("ldmatrix.sync.aligned.m8n8.x2.shared.b16 {%0,%1}, [%2];"
                 : "=r"(r[0]), "=r"(r[1]) : "r"(a));
}
__device__ __forceinline__ void mma16816(float* c, const uint32_t* a, const uint32_t* b) {
    asm volatile(
        "mma.sync.aligned.m16n8k16.row.col.f32.f16.f16.f32 "
        "{%0,%1,%2,%3}, {%4,%5,%6,%7}, {%8,%9}, {%0,%1,%2,%3};"
        : "+f"(c[0]), "+f"(c[1]), "+f"(c[2]), "+f"(c[3])
        : "r"(a[0]), "r"(a[1]), "r"(a[2]), "r"(a[3]), "r"(b[0]), "r"(b[1]));
}

// ---------------- phase 1: all independent prep work in ONE launch ----------------
#define P1_BLOCKS 10636

struct ProArgs {
    const float *x;
    const int   *ei, *et;
    const float *wq, *wk, *wv, *wiq, *wik, *wiv, *wo;
    const float *bq, *bk, *bv, *biq, *bik, *biv;
};

__global__ __launch_bounds__(256) void prologue_kernel(ProArgs a) {
    const int b   = blockIdx.x;
    const int tid = threadIdx.x;

    if (b < 3072) {                                   // ---- conv_wia ----
        const int w  = b >> 10;
        const int i  = (b & 1023) * 256 + tid;
        const float* W = (w == 0) ? a.wiq : (w == 1) ? a.wik : a.wiv;
        float4 v = ((const float4*)W)[i];
        __half2 h01, h23;
        h01.x = __float2half_rn(v.x); h01.y = __float2half_rn(v.y);
        h23.x = __float2half_rn(v.z); h23.y = __float2half_rn(v.w);
        __half* A = g_wia + (size_t)w * WPSZ;
        *(__half2*)(A + i * 4)     = h01;
        *(__half2*)(A + i * 4 + 2) = h23;
    } else if (b < 6144) {                            // ---- conv_wt ----
        const int bb = b - 3072;
        const int w  = bb >> 10;
        const int t2 = bb & 1023;
        const int n0 = (t2 & 31) * 32;
        const int k0 = (t2 >> 5) * 32;
        const float* W = (w == 0) ? a.wq : (w == 1) ? a.wk : a.wv;
        __shared__ float t[32][33];
        const int tx = tid & 31;
        const int ty = tid >> 5;
        #pragma unroll
        for (int r = ty; r < 32; r += 8)
            t[r][tx] = W[(size_t)(k0 + r) * FDIM + n0 + tx];
        __syncthreads();
        __half* B = g_wtb + (size_t)w * WPSZ;
        #pragma unroll
        for (int rr = ty; rr < 32; rr += 8)
            B[(size_t)(n0 + rr) * KP + k0 + tx] = __float2half_rn(t[tx][rr]);
    } else if (b < 7168) {                            // ---- wo cast ----
        const int i = (b - 6144) * 256 + tid;
        float4 v = ((const float4*)a.wo)[i];
        __half2 h01, h23;
        h01.x = __float2half_rn(v.x); h01.y = __float2half_rn(v.y);
        h23.x = __float2half_rn(v.z); h23.y = __float2half_rn(v.w);
        __half* A = g_wb + (size_t)3 * WPSZ;
        *(__half2*)(A + i * 4)     = h01;
        *(__half2*)(A + i * 4 + 2) = h23;
    } else if (b < 10240) {                           // ---- x cast ----
        const int i = (b - 7168) * 256 + tid;
        float4 v = ((const float4*)a.x)[i];
        __half2 h01, h23;
        h01.x = __float2half_rn(v.x); h01.y = __float2half_rn(v.y);
        h23.x = __float2half_rn(v.z); h23.y = __float2half_rn(v.w);
        *(__half2*)(g_ab + i * 4)     = h01;
        *(__half2*)(g_ab + i * 4 + 2) = h23;
    } else if (b < 10624) {                           // ---- edge scatter ----
        const int e = (b - 10240) * 256 + tid;
        int s = a.ei[e], d = a.ei[EE + e];
        int pos = atomicAdd(&g_cnt[s], 1);
        if (pos < MAXDEG) {
            g_ecol[s * MAXDEG + pos] = d | (a.et[e] << 20);
            g_eeid[s * MAXDEG + pos] = e;
        }
    } else {                                          // ---- bias fuse ----
        const int idx = b - 10624;
        const int z   = idx >> 2;
        const int n   = (idx & 3) * 256 + tid;
        const float* W  = ((z == 0) ? a.wiq : (z == 1) ? a.wik : a.wiv) + (size_t)n * FDIM;
        const float* bi = (z == 0) ? a.bq : (z == 1) ? a.bk : a.bv;
        const float* bo = (z == 0) ? a.biq : (z == 1) ? a.bik : a.biv;
        float s = 0.f;
        #pragma unroll 8
        for (int k = 0; k < FDIM; k++) s = fmaf(W[k], bi[k], s);
        g_bf[z * FDIM + n] = s + bo[n];
    }
}

// ---------------- mma.sync fp16 GEMM core ----------------
#define STAGE_BYTES 16384
#define GEMM_SMEM   (3 * STAGE_BYTES)

__device__ __forceinline__ void load_tile_pair(
    const __half* Abase, const __half* Bbase,
    int row0, int col0, int k0, uint32_t sA, uint32_t sB, int tid)
{
    #pragma unroll
    for (int i = 0; i < 2; i++) {
        int c   = tid + i * 256;
        int row = c >> 2;
        int kc  = c & 3;
        uint32_t soff = (uint32_t)(((row >> 3) * 4 + kc) * 128 + (row & 7) * 16);
        cp16(sA + soff, Abase + (size_t)(row0 + row) * KP + k0 + kc * 8);
        cp16(sB + soff, Bbase + (size_t)(col0 + row) * KP + k0 + kc * 8);
    }
}

// MODE 0: fp32 out + bias.  MODE 1: fp16 out + bias.  Row stride FDIM both.
template<int MODE>
__device__ __forceinline__ void gemm_core(
    int bx, int by,
    const __half* __restrict__ A, const __half* __restrict__ B,
    const float* __restrict__ bias, float* __restrict__ Yf,
    __half* __restrict__ Ys)
{
    extern __shared__ char smem[];
    const uint32_t sb = smem_u32(smem);
    const int tid  = threadIdx.x;
    const int wid  = tid >> 5;
    const int lane = tid & 31;
    const int wm   = wid & 1;
    const int wn   = wid >> 1;
    const int row0 = by << 7;
    const int col0 = bx << 7;

    const int g  = lane >> 3;
    const int r8 = lane & 7;
    const uint32_t aconst = (uint32_t)((wm * 8 + (g & 1)) * 512 + (g >> 1) * 128 + r8 * 16);
    const uint32_t bconst = (uint32_t)(wn * 4 * 512 + (g & 1) * 128 + r8 * 16);

    float acc[4][4][4];
    #pragma unroll
    for (int mt = 0; mt < 4; mt++)
        #pragma unroll
        for (int nt = 0; nt < 4; nt++)
            acc[mt][nt][0] = acc[mt][nt][1] = acc[mt][nt][2] = acc[mt][nt][3] = 0.f;

    load_tile_pair(A, B, row0, col0, 0, sb, sb + 8192, tid);
    asm volatile("cp.async.commit_group;" ::: "memory");
    load_tile_pair(A, B, row0, col0, 32, sb + STAGE_BYTES, sb + STAGE_BYTES + 8192, tid);
    asm volatile("cp.async.commit_group;" ::: "memory");

    int buf = 0;
    for (int t = 0; t < NTP; t++) {
        asm volatile("cp.async.wait_group 1;" ::: "memory");
        __syncthreads();

        int nbuf = buf + 1; if (nbuf == 3) nbuf = 0;
        int lbuf = nbuf + 1; if (lbuf == 3) lbuf = 0;
        if (t + 2 < NTP) {
            uint32_t ls = sb + (uint32_t)lbuf * STAGE_BYTES;
            load_tile_pair(A, B, row0, col0, (t + 2) * 32, ls, ls + 8192, tid);
        }
        asm volatile("cp.async.commit_group;" ::: "memory");

        const uint32_t Ab = sb + (uint32_t)buf * STAGE_BYTES;
        const uint32_t Bb = Ab + 8192;
        #pragma unroll
        for (int kt = 0; kt < 2; kt++) {
            uint32_t af[4][4], bfr[4][2];
            #pragma unroll
            for (int mt = 0; mt < 4; mt++)
                ldsm4(af[mt], Ab + aconst + (uint32_t)(mt * 1024 + kt * 256));
            #pragma unroll
            for (int nt = 0; nt < 4; nt++)
                ldsm2(bfr[nt], Bb + bconst + (uint32_t)(nt * 512 + kt * 256));
            #pragma unroll
            for (int mt = 0; mt < 4; mt++)
                #pragma unroll
                for (int nt = 0; nt < 4; nt++)
                    mma16816(acc[mt][nt], af[mt], bfr[nt]);
        }
        buf = nbuf;
    }

    const int mbase = row0 + wm * 64 + (lane >> 2);
    const int nbase = col0 + wn * 32 + (lane & 3) * 2;
    #pragma unroll
    for (int mt = 0; mt < 4; mt++) {
        #pragma unroll
        for (int nt = 0; nt < 4; nt++) {
            int m = mbase + mt * 16;
            int n = nbase + nt * 8;
            float2 b2 = *(const float2*)&bias[n];
            float y0 = acc[mt][nt][0] + b2.x, y1 = acc[mt][nt][1] + b2.y;
            float y2 = acc[mt][nt][2] + b2.x, y3 = acc[mt][nt][3] + b2.y;
            if (MODE == 0) {
                *(float2*)&Yf[(size_t)m * FDIM + n]       = make_float2(y0, y1);
                *(float2*)&Yf[(size_t)(m + 8) * FDIM + n] = make_float2(y2, y3);
            } else {
                __half2 h0, h1;
                h0.x = __float2half_rn(y0); h0.y = __float2half_rn(y1);
                h1.x = __float2half_rn(y2); h1.y = __float2half_rn(y3);
                *(__half2*)(Ys + (size_t)m * FDIM + n)       = h0;
                *(__half2*)(Ys + (size_t)(m + 8) * FDIM + n) = h1;
            }
        }
    }
}

// ---------------- phase 2: fuse GEMM (blocks 0..191) + csr dedup (192..3263) ----------------
#define P2_BLOCKS (192 + NN)

__global__ __launch_bounds__(256) void phase2_kernel() {
    if (blockIdx.x < 192) {
        const int b  = blockIdx.x;
        const int z  = b >> 6;
        const int bb = b & 63;
        gemm_core<1>(bb & 7, bb >> 3,
                     g_wia + (size_t)z * WPSZ, g_wtb + (size_t)z * WPSZ,
                     g_zb, nullptr, g_wb + (size_t)z * WPSZ);
        return;
    }
    const int n   = blockIdx.x - 192;
    const int tid = threadIdx.x;
    __shared__ int scol[MAXDEG], seid[MAXDEG];
    __shared__ int outc, sflag;
    if (tid == 0) { outc = 0; sflag = 0; }
    int cnt = g_cnt[n];
    if (cnt > MAXDEG) cnt = MAXDEG;
    if (tid < cnt) {
        scol[tid] = g_ecol[n * MAXDEG + tid];
        seid[tid] = g_eeid[n * MAXDEG + tid];
    }
    __syncthreads();
    if (tid < cnt) {
        int cj = scol[tid] & 0xFFFFF;
        int ej = seid[tid];
        bool win = true;
        for (int i = 0; i < cnt; i++)
            if ((scol[i] & 0xFFFFF) == cj && seid[i] > ej) { win = false; break; }
        if (win) {
            int pos = atomicAdd(&outc, 1);
            g_adj[n * MAXDEG + pos] = scol[tid];
            if (cj == n) sflag = 1;
        }
    }
    __syncthreads();
    if (tid == 0) {
        int d = outc;
        if (!sflag && d < MAXDEG) { g_adj[n * MAXDEG + d] = n | (4 << 20); d++; }
        g_deg[n] = d;
        g_cnt[n] = 0;           // reset for next graph replay (deterministic)
    }
}

// ---------------- phase 3: q2/k2/v2 (all fp16 out) ----------------
__global__ __launch_bounds__(256) void gemm_main_kernel() {
    const int z = blockIdx.z;
    __half* Ys = (z == 0) ? g_q2h : (z == 1) ? g_k2h : g_v2h;
    gemm_core<1>(blockIdx.x, blockIdx.y, g_ab, g_wb + (size_t)z * WPSZ,
                 g_bf + z * FDIM, nullptr, Ys);
}

// ---------------- phase 5: out = fl16(att) @ wo + bo ----------------
__global__ __launch_bounds__(256) void gemm_final_kernel(const float* bias, float* Y) {
    gemm_core<0>(blockIdx.x, blockIdx.y, g_abatt, g_wb + (size_t)3 * WPSZ, bias, Y, nullptr);
}

// ---------------- phase 4: sparse gather attention ----------------
// q read from smem INSIDE the (once-executed) score loop body -> short register
// lifetimes -> no spills at 64 regs, 2 CTAs/SM.
__global__ __launch_bounds__(512, 2) void attn_sparse_kernel(const float* __restrict__ etw)
{
    __shared__ __half q_s[FDIM];           // 2 KB
    __shared__ int    nbr_s[MAXDEG];
    __shared__ float  sc_s[16][MAXDEG];    // 16 KB
    __shared__ float  wsh_s[8];

    const int n    = blockIdx.x;
    const int tid  = threadIdx.x;
    const int hh   = tid >> 5;
    const int lane = tid & 31;

    if (tid < 4) wsh_s[tid + 1] = log1pf(expf(etw[tid]));
    ((uint32_t*)q_s)[tid] = ((const uint32_t*)(g_q2h + (size_t)n * FDIM))[tid];
    const int deg = g_deg[n];
    for (int j = tid; j < deg; j += 512) nbr_s[j] = g_adj[n * MAXDEG + j];
    __syncthreads();

    const uint4* qsp = (const uint4*)&q_s[hh * HD];   // smem, broadcast reads

    float mx = -1e30f;
    for (int base = 0; base < deg; base += 32) {
        int   j = base + lane;
        float s = -1e30f;
        if (j < deg) {
            int pk   = nbr_s[j];
            int m    = pk & 0xFFFFF;
            int code = pk >> 20;
            const uint4* kp = (const uint4*)(g_k2h + (size_t)m * FDIM + hh * HD);
            float a0 = 0.f, a1 = 0.f;
            #pragma unroll
            for (int i = 0; i < 8; i += 2) {
                uint4 ka = kp[i], kb = kp[i + 1];
                uint4 qa = qsp[i], qb = qsp[i + 1];
                float2 k0 = __half22float2(*(__half2*)&ka.x);
                float2 k1 = __half22float2(*(__half2*)&ka.y);
                float2 k2 = __half22float2(*(__half2*)&ka.z);
                float2 k3 = __half22float2(*(__half2*)&ka.w);
                float2 q0 = __half22float2(*(__half2*)&qa.x);
                float2 q1 = __half22float2(*(__half2*)&qa.y);
                float2 q2 = __half22float2(*(__half2*)&qa.z);
                float2 q3 = __half22float2(*(__half2*)&qa.w);
                a0 = fmaf(q0.x, k0.x, a0); a0 = fmaf(q0.y, k0.y, a0);
                a0 = fmaf(q1.x, k1.x, a0); a0 = fmaf(q1.y, k1.y, a0);
                a0 = fmaf(q2.x, k2.x, a0); a0 = fmaf(q2.y, k2.y, a0);
                a0 = fmaf(q3.x, k3.x, a0); a0 = fmaf(q3.y, k3.y, a0);
                float2 g0 = __half22float2(*(__half2*)&kb.x);
                float2 g1 = __half22float2(*(__half2*)&kb.y);
                float2 g2 = __half22float2(*(__half2*)&kb.z);
                float2 g3 = __half22float2(*(__half2*)&kb.w);
                float2 p0 = __half22float2(*(__half2*)&qb.x);
                float2 p1 = __half22float2(*(__half2*)&qb.y);
                float2 p2 = __half22float2(*(__half2*)&qb.z);
                float2 p3 = __half22float2(*(__half2*)&qb.w);
                a1 = fmaf(p0.x, g0.x, a1); a1 = fmaf(p0.y, g0.y, a1);
                a1 = fmaf(p1.x, g1.x, a1); a1 = fmaf(p1.y, g1.y, a1);
                a1 = fmaf(p2.x, g2.x, a1); a1 = fmaf(p2.y, g2.y, a1);
                a1 = fmaf(p3.x, g3.x, a1); a1 = fmaf(p3.y, g3.y, a1);
            }
            s = fmaf(a0 + a1, 0.125f, wsh_s[code]);
            sc_s[hh][j] = s;
        }
        mx = fmaxf(mx, s);
    }
    #pragma unroll
    for (int off = 16; off; off >>= 1)
        mx = fmaxf(mx, __shfl_xor_sync(0xffffffffu, mx, off));
    __syncwarp();

    float sum = 0.f;
    for (int j = lane; j < deg; j += 32) {
        float p = __expf(sc_s[hh][j] - mx);
        sc_s[hh][j] = p;
        sum += p;
    }
    #pragma unroll
    for (int off = 16; off; off >>= 1)
        sum += __shfl_xor_sync(0xffffffffu, sum, off);
    const float inv = 1.f / sum;
    __syncwarp();

    const int dof = hh * HD + lane * 2;
    float o0 = 0.f, o1 = 0.f;
    #pragma unroll 8
    for (int j = 0; j < deg; j++) {
        int   m = nbr_s[j] & 0xFFFFF;
        float p = sc_s[hh][j];
        float2 f = __half22float2(*(const __half2*)(g_v2h + (size_t)m * FDIM + dof));
        o0 = fmaf(p, f.x, o0);
        o1 = fmaf(p, f.y, o1);
    }
    __half2 h;
    h.x = __float2half_rn(o0 * inv);
    h.y = __float2half_rn(o1 * inv);
    *(__half2*)(g_abatt + (size_t)n * KP + dof) = h;
}

// ---------------- launch ----------------
extern "C" void kernel_launch(void* const* d_in, const int* in_sizes, int n_in,
                              void* d_out, int out_size) {
    ProArgs a;
    a.x   = (const float*)d_in[0];
    a.ei  = (const int*)d_in[1];
    a.et  = (const int*)d_in[2];
    const float* etw = (const float*)d_in[3];
    a.wq  = (const float*)d_in[4];   a.bq  = (const float*)d_in[5];
    a.wk  = (const float*)d_in[6];   a.bk  = (const float*)d_in[7];
    a.wv  = (const float*)d_in[8];   a.bv  = (const float*)d_in[9];
    a.wiq = (const float*)d_in[10];  a.biq = (const float*)d_in[11];
    a.wik = (const float*)d_in[12];  a.bik = (const float*)d_in[13];
    a.wiv = (const float*)d_in[14];  a.biv = (const float*)d_in[15];
    a.wo  = (const float*)d_in[16];
    const float* bo = (const float*)d_in[17];
    float* out = (float*)d_out;

    cudaFuncSetAttribute(phase2_kernel,     cudaFuncAttributeMaxDynamicSharedMemorySize, GEMM_SMEM);
    cudaFuncSetAttribute(gemm_main_kernel,  cudaFuncAttributeMaxDynamicSharedMemorySize, GEMM_SMEM);
    cudaFuncSetAttribute(gemm_final_kernel, cudaFuncAttributeMaxDynamicSharedMemorySize, GEMM_SMEM);

    prologue_kernel<<<P1_BLOCKS, 256>>>(a);
    phase2_kernel<<<P2_BLOCKS, 256, GEMM_SMEM>>>();
    gemm_main_kernel<<<dim3(FDIM / 128, NN / 128, 3), 256, GEMM_SMEM>>>();
    attn_sparse_kernel<<<NN, 512>>>(etw);
    gemm_final_kernel<<<dim3(FDIM / 128, NN / 128), 256, GEMM_SMEM>>>(bo, out);
}

// round 14
// speedup vs baseline: 1.3135x; 1.0031x over previous
#include <cuda_runtime.h>
#include <cuda_fp16.h>
#include <math.h>
#include <stdint.h>

#define NN     3072
#define EE     98304
#define FDIM   1024
#define HD     64
#define MAXDEG 256
#define KP     1024          // fp16 GEMM K
#define NTP    (KP / 32)     // 32 BK32 tiles
#define WPSZ   ((size_t)FDIM * KP)

// ---------------- scratch (static device arrays; no allocation) ----------------
__device__ int   g_cnt[NN];                   // zero-init; csr2 resets after use
__device__ int   g_ecol[NN * MAXDEG];
__device__ int   g_eeid[NN * MAXDEG];
__device__ int   g_adj[NN * MAXDEG];
__device__ int   g_deg[NN];
__device__ __half g_q2h[NN * FDIM];           // fp16 q2/k2/v2
__device__ __half g_k2h[NN * FDIM];
__device__ __half g_v2h[NN * FDIM];
__device__ float g_bf[3 * FDIM];              // fused biases
__device__ float g_zb[FDIM];                  // zero bias (static zero-init)
__device__ __half g_ab   [NN * KP];           // fp16 cast of x
__device__ __half g_abatt[NN * KP];           // fp16 cast of attn out
__device__ __half g_wia[3 * WPSZ];            // fp16 cast of Wiq/Wik/Wiv
__device__ __half g_wtb[3 * WPSZ];            // fp16 cast of Wq^T/Wk^T/Wv^T
__device__ __half g_wb [4 * WPSZ];            // fp16: Wf0..2 (from fuse), wo

// ---------------- PTX helpers ----------------
__device__ __forceinline__ uint32_t smem_u32(const void* p) {
    uint32_t a;
    asm("{ .reg .u64 t; cvta.to.shared.u64 t, %1; cvt.u32.u64 %0, t; }" : "=r"(a) : "l"(p));
    return a;
}
__device__ __forceinline__ void cp16(uint32_t dst, const void* src) {
    asm volatile("cp.async.cg.shared.global [%0], [%1], 16;" :: "r"(dst), "l"(src));
}
__device__ __forceinline__ void ldsm4(uint32_t* r, uint32_t a) {
    asm volatile("ldmatrix.sync.aligned.m8n8.x4.shared.b16 {%0,%1,%2,%3}, [%4];"
                 : "=r"(r[0]), "=r"(r[1]), "=r"(r[2]), "=r"(r[3]) : "r"(a));
}
__device__ __forceinline__ void ldsm2(uint32_t* r, uint32_t a) {
    asm volatile("ldmatrix.sync.aligned.m8n8.x2.shared.b16 {%0,%1}, [%2];"
                 : "=r"(r[0]), "=r"(r[1]) : "r"(a));
}
__device__ __forceinline__ void mma16816(float* c, const uint32_t* a, const uint32_t* b) {
    asm volatile(
        "mma.sync.aligned.m16n8k16.row.col.f32.f16.f16.f32 "
        "{%0,%1,%2,%3}, {%4,%5,%6,%7}, {%8,%9}, {%0,%1,%2,%3};"
        : "+f"(c[0]), "+f"(c[1]), "+f"(c[2]), "+f"(c[3])
        : "r"(a[0]), "r"(a[1]), "r"(a[2]), "r"(a[3]), "r"(b[0]), "r"(b[1]));
}

// ---------------- phase 1: all independent prep work in ONE launch ----------------
#define P1_BLOCKS 10636

struct ProArgs {
    const float *x;
    const int   *ei, *et;
    const float *wq, *wk, *wv, *wiq, *wik, *wiv, *wo;
    const float *bq, *bk, *bv, *biq, *bik, *biv;
};

__global__ __launch_bounds__(256) void prologue_kernel(ProArgs a) {
    const int b   = blockIdx.x;
    const int tid = threadIdx.x;

    if (b < 3072) {                                   // ---- conv_wia ----
        const int w  = b >> 10;
        const int i  = (b & 1023) * 256 + tid;
        const float* W = (w == 0) ? a.wiq : (w == 1) ? a.wik : a.wiv;
        float4 v = ((const float4*)W)[i];
        __half2 h01, h23;
        h01.x = __float2half_rn(v.x); h01.y = __float2half_rn(v.y);
        h23.x = __float2half_rn(v.z); h23.y = __float2half_rn(v.w);
        __half* A = g_wia + (size_t)w * WPSZ;
        *(__half2*)(A + i * 4)     = h01;
        *(__half2*)(A + i * 4 + 2) = h23;
    } else if (b < 6144) {                            // ---- conv_wt ----
        const int bb = b - 3072;
        const int w  = bb >> 10;
        const int t2 = bb & 1023;
        const int n0 = (t2 & 31) * 32;
        const int k0 = (t2 >> 5) * 32;
        const float* W = (w == 0) ? a.wq : (w == 1) ? a.wk : a.wv;
        __shared__ float t[32][33];
        const int tx = tid & 31;
        const int ty = tid >> 5;
        #pragma unroll
        for (int r = ty; r < 32; r += 8)
            t[r][tx] = W[(size_t)(k0 + r) * FDIM + n0 + tx];
        __syncthreads();
        __half* B = g_wtb + (size_t)w * WPSZ;
        #pragma unroll
        for (int rr = ty; rr < 32; rr += 8)
            B[(size_t)(n0 + rr) * KP + k0 + tx] = __float2half_rn(t[tx][rr]);
    } else if (b < 7168) {                            // ---- wo cast ----
        const int i = (b - 6144) * 256 + tid;
        float4 v = ((const float4*)a.wo)[i];
        __half2 h01, h23;
        h01.x = __float2half_rn(v.x); h01.y = __float2half_rn(v.y);
        h23.x = __float2half_rn(v.z); h23.y = __float2half_rn(v.w);
        __half* A = g_wb + (size_t)3 * WPSZ;
        *(__half2*)(A + i * 4)     = h01;
        *(__half2*)(A + i * 4 + 2) = h23;
    } else if (b < 10240) {                           // ---- x cast ----
        const int i = (b - 7168) * 256 + tid;
        float4 v = ((const float4*)a.x)[i];
        __half2 h01, h23;
        h01.x = __float2half_rn(v.x); h01.y = __float2half_rn(v.y);
        h23.x = __float2half_rn(v.z); h23.y = __float2half_rn(v.w);
        *(__half2*)(g_ab + i * 4)     = h01;
        *(__half2*)(g_ab + i * 4 + 2) = h23;
    } else if (b < 10624) {                           // ---- edge scatter ----
        const int e = (b - 10240) * 256 + tid;
        int s = a.ei[e], d = a.ei[EE + e];
        int pos = atomicAdd(&g_cnt[s], 1);
        if (pos < MAXDEG) {
            g_ecol[s * MAXDEG + pos] = d | (a.et[e] << 20);
            g_eeid[s * MAXDEG + pos] = e;
        }
    } else {                                          // ---- bias fuse ----
        const int idx = b - 10624;
        const int z   = idx >> 2;
        const int n   = (idx & 3) * 256 + tid;
        const float* W  = ((z == 0) ? a.wiq : (z == 1) ? a.wik : a.wiv) + (size_t)n * FDIM;
        const float* bi = (z == 0) ? a.bq : (z == 1) ? a.bk : a.bv;
        const float* bo = (z == 0) ? a.biq : (z == 1) ? a.bik : a.biv;
        float s = 0.f;
        #pragma unroll 8
        for (int k = 0; k < FDIM; k++) s = fmaf(W[k], bi[k], s);
        g_bf[z * FDIM + n] = s + bo[n];
    }
}

// ---------------- mma.sync fp16 GEMM core ----------------
#define STAGE_BYTES 16384
#define GEMM_SMEM   (3 * STAGE_BYTES)

__device__ __forceinline__ void load_tile_pair(
    const __half* Abase, const __half* Bbase,
    int row0, int col0, int k0, uint32_t sA, uint32_t sB, int tid)
{
    #pragma unroll
    for (int i = 0; i < 2; i++) {
        int c   = tid + i * 256;
        int row = c >> 2;
        int kc  = c & 3;
        uint32_t soff = (uint32_t)(((row >> 3) * 4 + kc) * 128 + (row & 7) * 16);
        cp16(sA + soff, Abase + (size_t)(row0 + row) * KP + k0 + kc * 8);
        cp16(sB + soff, Bbase + (size_t)(col0 + row) * KP + k0 + kc * 8);
    }
}

// MODE 0: fp32 out + bias.  MODE 1: fp16 out + bias.  Row stride FDIM both.
template<int MODE>
__device__ __forceinline__ void gemm_core(
    int bx, int by,
    const __half* __restrict__ A, const __half* __restrict__ B,
    const float* __restrict__ bias, float* __restrict__ Yf,
    __half* __restrict__ Ys)
{
    extern __shared__ char smem[];
    const uint32_t sb = smem_u32(smem);
    const int tid  = threadIdx.x;
    const int wid  = tid >> 5;
    const int lane = tid & 31;
    const int wm   = wid & 1;
    const int wn   = wid >> 1;
    const int row0 = by << 7;
    const int col0 = bx << 7;

    const int g  = lane >> 3;
    const int r8 = lane & 7;
    const uint32_t aconst = (uint32_t)((wm * 8 + (g & 1)) * 512 + (g >> 1) * 128 + r8 * 16);
    const uint32_t bconst = (uint32_t)(wn * 4 * 512 + (g & 1) * 128 + r8 * 16);

    float acc[4][4][4];
    #pragma unroll
    for (int mt = 0; mt < 4; mt++)
        #pragma unroll
        for (int nt = 0; nt < 4; nt++)
            acc[mt][nt][0] = acc[mt][nt][1] = acc[mt][nt][2] = acc[mt][nt][3] = 0.f;

    load_tile_pair(A, B, row0, col0, 0, sb, sb + 8192, tid);
    asm volatile("cp.async.commit_group;" ::: "memory");
    load_tile_pair(A, B, row0, col0, 32, sb + STAGE_BYTES, sb + STAGE_BYTES + 8192, tid);
    asm volatile("cp.async.commit_group;" ::: "memory");

    int buf = 0;
    for (int t = 0; t < NTP; t++) {
        asm volatile("cp.async.wait_group 1;" ::: "memory");
        __syncthreads();

        int nbuf = buf + 1; if (nbuf == 3) nbuf = 0;
        int lbuf = nbuf + 1; if (lbuf == 3) lbuf = 0;
        if (t + 2 < NTP) {
            uint32_t ls = sb + (uint32_t)lbuf * STAGE_BYTES;
            load_tile_pair(A, B, row0, col0, (t + 2) * 32, ls, ls + 8192, tid);
        }
        asm volatile("cp.async.commit_group;" ::: "memory");

        const uint32_t Ab = sb + (uint32_t)buf * STAGE_BYTES;
        const uint32_t Bb = Ab + 8192;
        #pragma unroll
        for (int kt = 0; kt < 2; kt++) {
            uint32_t af[4][4], bfr[4][2];
            #pragma unroll
            for (int mt = 0; mt < 4; mt++)
                ldsm4(af[mt], Ab + aconst + (uint32_t)(mt * 1024 + kt * 256));
            #pragma unroll
            for (int nt = 0; nt < 4; nt++)
                ldsm2(bfr[nt], Bb + bconst + (uint32_t)(nt * 512 + kt * 256));
            #pragma unroll
            for (int mt = 0; mt < 4; mt++)
                #pragma unroll
                for (int nt = 0; nt < 4; nt++)
                    mma16816(acc[mt][nt], af[mt], bfr[nt]);
        }
        buf = nbuf;
    }

    const int mbase = row0 + wm * 64 + (lane >> 2);
    const int nbase = col0 + wn * 32 + (lane & 3) * 2;
    #pragma unroll
    for (int mt = 0; mt < 4; mt++) {
        #pragma unroll
        for (int nt = 0; nt < 4; nt++) {
            int m = mbase + mt * 16;
            int n = nbase + nt * 8;
            float2 b2 = *(const float2*)&bias[n];
            float y0 = acc[mt][nt][0] + b2.x, y1 = acc[mt][nt][1] + b2.y;
            float y2 = acc[mt][nt][2] + b2.x, y3 = acc[mt][nt][3] + b2.y;
            if (MODE == 0) {
                *(float2*)&Yf[(size_t)m * FDIM + n]       = make_float2(y0, y1);
                *(float2*)&Yf[(size_t)(m + 8) * FDIM + n] = make_float2(y2, y3);
            } else {
                __half2 h0, h1;
                h0.x = __float2half_rn(y0); h0.y = __float2half_rn(y1);
                h1.x = __float2half_rn(y2); h1.y = __float2half_rn(y3);
                *(__half2*)(Ys + (size_t)m * FDIM + n)       = h0;
                *(__half2*)(Ys + (size_t)(m + 8) * FDIM + n) = h1;
            }
        }
    }
}

// ---------------- phase 2: fuse GEMM (blocks 0..191) + csr dedup (192..3263) ----------------
#define P2_BLOCKS (192 + NN)

__global__ __launch_bounds__(256) void phase2_kernel() {
    if (blockIdx.x < 192) {
        const int b  = blockIdx.x;
        const int z  = b >> 6;
        const int bb = b & 63;
        gemm_core<1>(bb & 7, bb >> 3,
                     g_wia + (size_t)z * WPSZ, g_wtb + (size_t)z * WPSZ,
                     g_zb, nullptr, g_wb + (size_t)z * WPSZ);
        return;
    }
    const int n   = blockIdx.x - 192;
    const int tid = threadIdx.x;
    __shared__ int scol[MAXDEG], seid[MAXDEG];
    __shared__ int outc, sflag;
    if (tid == 0) { outc = 0; sflag = 0; }
    int cnt = g_cnt[n];
    if (cnt > MAXDEG) cnt = MAXDEG;
    if (tid < cnt) {
        scol[tid] = g_ecol[n * MAXDEG + tid];
        seid[tid] = g_eeid[n * MAXDEG + tid];
    }
    __syncthreads();
    if (tid < cnt) {
        int cj = scol[tid] & 0xFFFFF;
        int ej = seid[tid];
        bool win = true;
        for (int i = 0; i < cnt; i++)
            if ((scol[i] & 0xFFFFF) == cj && seid[i] > ej) { win = false; break; }
        if (win) {
            int pos = atomicAdd(&outc, 1);
            g_adj[n * MAXDEG + pos] = scol[tid];
            if (cj == n) sflag = 1;
        }
    }
    __syncthreads();
    if (tid == 0) {
        int d = outc;
        if (!sflag && d < MAXDEG) { g_adj[n * MAXDEG + d] = n | (4 << 20); d++; }
        g_deg[n] = d;
        g_cnt[n] = 0;           // reset for next graph replay (deterministic)
    }
}

// ---------------- phase 3: q2/k2/v2 (all fp16 out) ----------------
__global__ __launch_bounds__(256) void gemm_main_kernel() {
    const int z = blockIdx.z;
    __half* Ys = (z == 0) ? g_q2h : (z == 1) ? g_k2h : g_v2h;
    gemm_core<1>(blockIdx.x, blockIdx.y, g_ab, g_wb + (size_t)z * WPSZ,
                 g_bf + z * FDIM, nullptr, Ys);
}

// ---------------- phase 5: out = fl16(att) @ wo + bo ----------------
__global__ __launch_bounds__(256) void gemm_final_kernel(const float* bias, float* Y) {
    gemm_core<0>(blockIdx.x, blockIdx.y, g_abatt, g_wb + (size_t)3 * WPSZ, bias, Y, nullptr);
}

// ---------------- phase 4: sparse gather attention ----------------
// Score phase: lanes over dims (coalesced 128B line per neighbor) + butterfly
// reduce. PV phase: lanes over dims (already coalesced). 2 CTAs/SM.
__global__ __launch_bounds__(512, 2) void attn_sparse_kernel(const float* __restrict__ etw)
{
    __shared__ __half q_s[FDIM];           // 2 KB
    __shared__ int    nbr_s[MAXDEG];
    __shared__ float  sc_s[16][MAXDEG];    // 16 KB
    __shared__ float  wsh_s[8];

    const int n    = blockIdx.x;
    const int tid  = threadIdx.x;
    const int hh   = tid >> 5;
    const int lane = tid & 31;

    if (tid < 4) wsh_s[tid + 1] = log1pf(expf(etw[tid]));
    ((uint32_t*)q_s)[tid] = ((const uint32_t*)(g_q2h + (size_t)n * FDIM))[tid];
    const int deg = g_deg[n];
    for (int j = tid; j < deg; j += 512) nbr_s[j] = g_adj[n * MAXDEG + j];
    __syncthreads();

    const int dof = hh * HD + lane * 2;     // this lane's 2 dims of head hh
    const float2 qf = __half22float2(*(const __half2*)&q_s[dof]);

    // ---- scores: serial over neighbors, coalesced k loads, butterfly reduce ----
    float mx = -1e30f;
    #pragma unroll 4
    for (int j = 0; j < deg; j++) {
        int pk   = nbr_s[j];
        int m    = pk & 0xFFFFF;
        int code = pk >> 20;
        float2 kf = __half22float2(*(const __half2*)(g_k2h + (size_t)m * FDIM + dof));
        float part = fmaf(qf.x, kf.x, qf.y * kf.y);
        #pragma unroll
        for (int off = 16; off; off >>= 1)
            part += __shfl_xor_sync(0xffffffffu, part, off);
        float s = fmaf(part, 0.125f, wsh_s[code]);
        if (lane == 0) sc_s[hh][j] = s;
        mx = fmaxf(mx, s);                 // all lanes hold full score
    }
    __syncwarp();

    // ---- softmax over the list ----
    float sum = 0.f;
    for (int j = lane; j < deg; j += 32) {
        float p = __expf(sc_s[hh][j] - mx);
        sc_s[hh][j] = p;
        sum += p;
    }
    #pragma unroll
    for (int off = 16; off; off >>= 1)
        sum += __shfl_xor_sync(0xffffffffu, sum, off);
    const float inv = 1.f / sum;
    __syncwarp();

    // ---- PV: lanes over dims, serial neighbors (coalesced) ----
    float o0 = 0.f, o1 = 0.f;
    #pragma unroll 8
    for (int j = 0; j < deg; j++) {
        int   m = nbr_s[j] & 0xFFFFF;
        float p = sc_s[hh][j];
        float2 f = __half22float2(*(const __half2*)(g_v2h + (size_t)m * FDIM + dof));
        o0 = fmaf(p, f.x, o0);
        o1 = fmaf(p, f.y, o1);
    }
    __half2 h;
    h.x = __float2half_rn(o0 * inv);
    h.y = __float2half_rn(o1 * inv);
    *(__half2*)(g_abatt + (size_t)n * KP + dof) = h;
}

// ---------------- launch ----------------
extern "C" void kernel_launch(void* const* d_in, const int* in_sizes, int n_in,
                              void* d_out, int out_size) {
    ProArgs a;
    a.x   = (const float*)d_in[0];
    a.ei  = (const int*)d_in[1];
    a.et  = (const int*)d_in[2];
    const float* etw = (const float*)d_in[3];
    a.wq  = (const float*)d_in[4];   a.bq  = (const float*)d_in[5];
    a.wk  = (const float*)d_in[6];   a.bk  = (const float*)d_in[7];
    a.wv  = (const float*)d_in[8];   a.bv  = (const float*)d_in[9];
    a.wiq = (const float*)d_in[10];  a.biq = (const float*)d_in[11];
    a.wik = (const float*)d_in[12];  a.bik = (const float*)d_in[13];
    a.wiv = (const float*)d_in[14];  a.biv = (const float*)d_in[15];
    a.wo  = (const float*)d_in[16];
    const float* bo = (const float*)d_in[17];
    float* out = (float*)d_out;

    cudaFuncSetAttribute(phase2_kernel,     cudaFuncAttributeMaxDynamicSharedMemorySize, GEMM_SMEM);
    cudaFuncSetAttribute(gemm_main_kernel,  cudaFuncAttributeMaxDynamicSharedMemorySize, GEMM_SMEM);
    cudaFuncSetAttribute(gemm_final_kernel, cudaFuncAttributeMaxDynamicSharedMemorySize, GEMM_SMEM);

    prologue_kernel<<<P1_BLOCKS, 256>>>(a);
    phase2_kernel<<<P2_BLOCKS, 256, GEMM_SMEM>>>();
    gemm_main_kernel<<<dim3(FDIM / 128, NN / 128, 3), 256, GEMM_SMEM>>>();
    attn_sparse_kernel<<<NN, 512>>>(etw);
    gemm_final_kernel<<<dim3(FDIM / 128, NN / 128), 256, GEMM_SMEM>>>(bo, out);
}

// round 16
// speedup vs baseline: 1.3984x; 1.0646x over previous
#include <cuda_runtime.h>
#include <cuda_fp16.h>
#include <math.h>
#include <stdint.h>

#define NN     3072
#define EE     98304
#define FDIM   1024
#define HD     64
#define MAXDEG 256
#define KP     1024          // fp16 GEMM K
#define NTP    (KP / 32)     // 32 BK32 tiles
#define WPSZ   ((size_t)FDIM * KP)

// ---------------- scratch (static device arrays; no allocation) ----------------
__device__ int   g_cnt[NN];                   // zero-init; csr2 resets after use
__device__ int   g_ecol[NN * MAXDEG];
__device__ int   g_eeid[NN * MAXDEG];
__device__ int   g_adj[NN * MAXDEG];
__device__ int   g_deg[NN];
__device__ __half g_q2h[NN * FDIM];           // fp16 q2/k2/v2
__device__ __half g_k2h[NN * FDIM];
__device__ __half g_v2h[NN * FDIM];
__device__ float g_bf[3 * FDIM];              // fused biases
__device__ float g_zb[FDIM];                  // zero bias (static zero-init)
__device__ __half g_ab   [NN * KP];           // fp16 cast of x
__device__ __half g_abatt[NN * KP];           // fp16 cast of attn out
__device__ __half g_wia[3 * WPSZ];            // fp16 cast of Wiq/Wik/Wiv
__device__ __half g_wtb[3 * WPSZ];            // fp16 cast of Wq^T/Wk^T/Wv^T
__device__ __half g_wb [4 * WPSZ];            // fp16: Wf0..2 (from fuse), wo

// ---------------- PTX helpers ----------------
__device__ __forceinline__ uint32_t smem_u32(const void* p) {
    uint32_t a;
    asm("{ .reg .u64 t; cvta.to.shared.u64 t, %1; cvt.u32.u64 %0, t; }" : "=r"(a) : "l"(p));
    return a;
}
__device__ __forceinline__ void cp16(uint32_t dst, const void* src) {
    asm volatile("cp.async.cg.shared.global [%0], [%1], 16;" :: "r"(dst), "l"(src));
}
__device__ __forceinline__ void ldsm4(uint32_t* r, uint32_t a) {
    asm volatile("ldmatrix.sync.aligned.m8n8.x4.shared.b16 {%0,%1,%2,%3}, [%4];"
                 : "=r"(r[0]), "=r"(r[1]), "=r"(r[2]), "=r"(r[3]) : "r"(a));
}
__device__ __forceinline__ void ldsm2(uint32_t* r, uint32_t a) {
    asm volatile("ldmatrix.sync.aligned.m8n8.x2.shared.b16 {%0,%1}, [%2];"
                 : "=r"(r[0]), "=r"(r[1]) : "r"(a));
}
__device__ __forceinline__ void mma16816(float* c, const uint32_t* a, const uint32_t* b) {
    asm volatile(
        "mma.sync.aligned.m16n8k16.row.col.f32.f16.f16.f32 "
        "{%0,%1,%2,%3}, {%4,%5,%6,%7}, {%8,%9}, {%0,%1,%2,%3};"
        : "+f"(c[0]), "+f"(c[1]), "+f"(c[2]), "+f"(c[3])
        : "r"(a[0]), "r"(a[1]), "r"(a[2]), "r"(a[3]), "r"(b[0]), "r"(b[1]));
}

// ---------------- phase 1: all independent prep work in ONE launch ----------------
#define P1_BLOCKS 10636

struct ProArgs {
    const float *x;
    const int   *ei, *et;
    const float *wq, *wk, *wv, *wiq, *wik, *wiv, *wo;
    const float *bq, *bk, *bv, *biq, *bik, *biv;
};

__global__ __launch_bounds__(256) void prologue_kernel(ProArgs a) {
    const int b   = blockIdx.x;
    const int tid = threadIdx.x;

    if (b < 3072) {                                   // ---- conv_wia ----
        const int w  = b >> 10;
        const int i  = (b & 1023) * 256 + tid;
        const float* W = (w == 0) ? a.wiq : (w == 1) ? a.wik : a.wiv;
        float4 v = ((const float4*)W)[i];
        __half2 h01, h23;
        h01.x = __float2half_rn(v.x); h01.y = __float2half_rn(v.y);
        h23.x = __float2half_rn(v.z); h23.y = __float2half_rn(v.w);
        __half* A = g_wia + (size_t)w * WPSZ;
        *(__half2*)(A + i * 4)     = h01;
        *(__half2*)(A + i * 4 + 2) = h23;
    } else if (b < 6144) {                            // ---- conv_wt ----
        const int bb = b - 3072;
        const int w  = bb >> 10;
        const int t2 = bb & 1023;
        const int n0 = (t2 & 31) * 32;
        const int k0 = (t2 >> 5) * 32;
        const float* W = (w == 0) ? a.wq : (w == 1) ? a.wk : a.wv;
        __shared__ float t[32][33];
        const int tx = tid & 31;
        const int ty = tid >> 5;
        #pragma unroll
        for (int r = ty; r < 32; r += 8)
            t[r][tx] = W[(size_t)(k0 + r) * FDIM + n0 + tx];
        __syncthreads();
        __half* B = g_wtb + (size_t)w * WPSZ;
        #pragma unroll
        for (int rr = ty; rr < 32; rr += 8)
            B[(size_t)(n0 + rr) * KP + k0 + tx] = __float2half_rn(t[tx][rr]);
    } else if (b < 7168) {                            // ---- wo cast ----
        const int i = (b - 6144) * 256 + tid;
        float4 v = ((const float4*)a.wo)[i];
        __half2 h01, h23;
        h01.x = __float2half_rn(v.x); h01.y = __float2half_rn(v.y);
        h23.x = __float2half_rn(v.z); h23.y = __float2half_rn(v.w);
        __half* A = g_wb + (size_t)3 * WPSZ;
        *(__half2*)(A + i * 4)     = h01;
        *(__half2*)(A + i * 4 + 2) = h23;
    } else if (b < 10240) {                           // ---- x cast ----
        const int i = (b - 7168) * 256 + tid;
        float4 v = ((const float4*)a.x)[i];
        __half2 h01, h23;
        h01.x = __float2half_rn(v.x); h01.y = __float2half_rn(v.y);
        h23.x = __float2half_rn(v.z); h23.y = __float2half_rn(v.w);
        *(__half2*)(g_ab + i * 4)     = h01;
        *(__half2*)(g_ab + i * 4 + 2) = h23;
    } else if (b < 10624) {                           // ---- edge scatter ----
        const int e = (b - 10240) * 256 + tid;
        int s = a.ei[e], d = a.ei[EE + e];
        int pos = atomicAdd(&g_cnt[s], 1);
        if (pos < MAXDEG) {
            g_ecol[s * MAXDEG + pos] = d | (a.et[e] << 20);
            g_eeid[s * MAXDEG + pos] = e;
        }
    } else {                                          // ---- bias fuse ----
        const int idx = b - 10624;
        const int z   = idx >> 2;
        const int n   = (idx & 3) * 256 + tid;
        const float* W  = ((z == 0) ? a.wiq : (z == 1) ? a.wik : a.wiv) + (size_t)n * FDIM;
        const float* bi = (z == 0) ? a.bq : (z == 1) ? a.bk : a.bv;
        const float* bo = (z == 0) ? a.biq : (z == 1) ? a.bik : a.biv;
        float s = 0.f;
        #pragma unroll 8
        for (int k = 0; k < FDIM; k++) s = fmaf(W[k], bi[k], s);
        g_bf[z * FDIM + n] = s + bo[n];
    }
}

// ---------------- mma.sync fp16 GEMM core ----------------
#define STAGE_BYTES 16384
#define GEMM_SMEM   (3 * STAGE_BYTES)

__device__ __forceinline__ void load_tile_pair(
    const __half* Abase, const __half* Bbase,
    int row0, int col0, int k0, uint32_t sA, uint32_t sB, int tid)
{
    #pragma unroll
    for (int i = 0; i < 2; i++) {
        int c   = tid + i * 256;
        int row = c >> 2;
        int kc  = c & 3;
        uint32_t soff = (uint32_t)(((row >> 3) * 4 + kc) * 128 + (row & 7) * 16);
        cp16(sA + soff, Abase + (size_t)(row0 + row) * KP + k0 + kc * 8);
        cp16(sB + soff, Bbase + (size_t)(col0 + row) * KP + k0 + kc * 8);
    }
}

// MODE 0: fp32 out + bias.  MODE 1: fp16 out + bias.  Row stride FDIM both.
template<int MODE>
__device__ __forceinline__ void gemm_core(
    int bx, int by,
    const __half* __restrict__ A, const __half* __restrict__ B,
    const float* __restrict__ bias, float* __restrict__ Yf,
    __half* __restrict__ Ys)
{
    extern __shared__ char smem[];
    const uint32_t sb = smem_u32(smem);
    const int tid  = threadIdx.x;
    const int wid  = tid >> 5;
    const int lane = tid & 31;
    const int wm   = wid & 1;
    const int wn   = wid >> 1;
    const int row0 = by << 7;
    const int col0 = bx << 7;

    const int g  = lane >> 3;
    const int r8 = lane & 7;
    const uint32_t aconst = (uint32_t)((wm * 8 + (g & 1)) * 512 + (g >> 1) * 128 + r8 * 16);
    const uint32_t bconst = (uint32_t)(wn * 4 * 512 + (g & 1) * 128 + r8 * 16);

    float acc[4][4][4];
    #pragma unroll
    for (int mt = 0; mt < 4; mt++)
        #pragma unroll
        for (int nt = 0; nt < 4; nt++)
            acc[mt][nt][0] = acc[mt][nt][1] = acc[mt][nt][2] = acc[mt][nt][3] = 0.f;

    load_tile_pair(A, B, row0, col0, 0, sb, sb + 8192, tid);
    asm volatile("cp.async.commit_group;" ::: "memory");
    load_tile_pair(A, B, row0, col0, 32, sb + STAGE_BYTES, sb + STAGE_BYTES + 8192, tid);
    asm volatile("cp.async.commit_group;" ::: "memory");

    int buf = 0;
    for (int t = 0; t < NTP; t++) {
        asm volatile("cp.async.wait_group 1;" ::: "memory");
        __syncthreads();

        int nbuf = buf + 1; if (nbuf == 3) nbuf = 0;
        int lbuf = nbuf + 1; if (lbuf == 3) lbuf = 0;
        if (t + 2 < NTP) {
            uint32_t ls = sb + (uint32_t)lbuf * STAGE_BYTES;
            load_tile_pair(A, B, row0, col0, (t + 2) * 32, ls, ls + 8192, tid);
        }
        asm volatile("cp.async.commit_group;" ::: "memory");

        const uint32_t Ab = sb + (uint32_t)buf * STAGE_BYTES;
        const uint32_t Bb = Ab + 8192;
        #pragma unroll
        for (int kt = 0; kt < 2; kt++) {
            uint32_t af[4][4], bfr[4][2];
            #pragma unroll
            for (int mt = 0; mt < 4; mt++)
                ldsm4(af[mt], Ab + aconst + (uint32_t)(mt * 1024 + kt * 256));
            #pragma unroll
            for (int nt = 0; nt < 4; nt++)
                ldsm2(bfr[nt], Bb + bconst + (uint32_t)(nt * 512 + kt * 256));
            #pragma unroll
            for (int mt = 0; mt < 4; mt++)
                #pragma unroll
                for (int nt = 0; nt < 4; nt++)
                    mma16816(acc[mt][nt], af[mt], bfr[nt]);
        }
        buf = nbuf;
    }

    const int mbase = row0 + wm * 64 + (lane >> 2);
    const int nbase = col0 + wn * 32 + (lane & 3) * 2;
    #pragma unroll
    for (int mt = 0; mt < 4; mt++) {
        #pragma unroll
        for (int nt = 0; nt < 4; nt++) {
            int m = mbase + mt * 16;
            int n = nbase + nt * 8;
            float2 b2 = *(const float2*)&bias[n];
            float y0 = acc[mt][nt][0] + b2.x, y1 = acc[mt][nt][1] + b2.y;
            float y2 = acc[mt][nt][2] + b2.x, y3 = acc[mt][nt][3] + b2.y;
            if (MODE == 0) {
                *(float2*)&Yf[(size_t)m * FDIM + n]       = make_float2(y0, y1);
                *(float2*)&Yf[(size_t)(m + 8) * FDIM + n] = make_float2(y2, y3);
            } else {
                __half2 h0, h1;
                h0.x = __float2half_rn(y0); h0.y = __float2half_rn(y1);
                h1.x = __float2half_rn(y2); h1.y = __float2half_rn(y3);
                *(__half2*)(Ys + (size_t)m * FDIM + n)       = h0;
                *(__half2*)(Ys + (size_t)(m + 8) * FDIM + n) = h1;
            }
        }
    }
}

// ---------------- phase 2: fuse GEMM (blocks 0..191) + csr dedup (192..3263) ----------------
#define P2_BLOCKS (192 + NN)

__global__ __launch_bounds__(256) void phase2_kernel() {
    if (blockIdx.x < 192) {
        const int b  = blockIdx.x;
        const int z  = b >> 6;
        const int bb = b & 63;
        gemm_core<1>(bb & 7, bb >> 3,
                     g_wia + (size_t)z * WPSZ, g_wtb + (size_t)z * WPSZ,
                     g_zb, nullptr, g_wb + (size_t)z * WPSZ);
        return;
    }
    const int n   = blockIdx.x - 192;
    const int tid = threadIdx.x;
    __shared__ int scol[MAXDEG], seid[MAXDEG];
    __shared__ int outc, sflag;
    if (tid == 0) { outc = 0; sflag = 0; }
    int cnt = g_cnt[n];
    if (cnt > MAXDEG) cnt = MAXDEG;
    if (tid < cnt) {
        scol[tid] = g_ecol[n * MAXDEG + tid];
        seid[tid] = g_eeid[n * MAXDEG + tid];
    }
    __syncthreads();
    if (tid < cnt) {
        int cj = scol[tid] & 0xFFFFF;
        int ej = seid[tid];
        bool win = true;
        for (int i = 0; i < cnt; i++)
            if ((scol[i] & 0xFFFFF) == cj && seid[i] > ej) { win = false; break; }
        if (win) {
            int pos = atomicAdd(&outc, 1);
            g_adj[n * MAXDEG + pos] = scol[tid];
            if (cj == n) sflag = 1;
        }
    }
    __syncthreads();
    if (tid == 0) {
        int d = outc;
        if (!sflag && d < MAXDEG) { g_adj[n * MAXDEG + d] = n | (4 << 20); d++; }
        g_deg[n] = d;
        g_cnt[n] = 0;           // reset for next graph replay (deterministic)
    }
}

// ---------------- phase 3: q2/k2/v2 (all fp16 out) ----------------
__global__ __launch_bounds__(256) void gemm_main_kernel() {
    const int z = blockIdx.z;
    __half* Ys = (z == 0) ? g_q2h : (z == 1) ? g_k2h : g_v2h;
    gemm_core<1>(blockIdx.x, blockIdx.y, g_ab, g_wb + (size_t)z * WPSZ,
                 g_bf + z * FDIM, nullptr, Ys);
}

// ---------------- phase 5: out = fl16(att) @ wo + bo ----------------
__global__ __launch_bounds__(256) void gemm_final_kernel(const float* bias, float* Y) {
    gemm_core<0>(blockIdx.x, blockIdx.y, g_abatt, g_wb + (size_t)3 * WPSZ, bias, Y, nullptr);
}

// ---------------- phase 4: sparse gather attention ----------------
// Score phase: 4 groups of 8 lanes, each group handles one neighbor (8 dims/lane),
// width-8 butterfly => 0.75 shuffles/neighbor. PV: lanes over dims (coalesced).
__global__ __launch_bounds__(512, 2) void attn_sparse_kernel(const float* __restrict__ etw)
{
    __shared__ __half q_s[FDIM];           // 2 KB
    __shared__ int    nbr_s[MAXDEG];
    __shared__ float  sc_s[16][MAXDEG];    // 16 KB
    __shared__ float  wsh_s[8];

    const int n    = blockIdx.x;
    const int tid  = threadIdx.x;
    const int hh   = tid >> 5;
    const int lane = tid & 31;

    if (tid < 4) wsh_s[tid + 1] = log1pf(expf(etw[tid]));
    ((uint32_t*)q_s)[tid] = ((const uint32_t*)(g_q2h + (size_t)n * FDIM))[tid];
    const int deg = g_deg[n];
    for (int j = tid; j < deg; j += 512) nbr_s[j] = g_adj[n * MAXDEG + j];
    __syncthreads();

    const int grp = lane >> 3;              // neighbor group 0..3
    const int sl  = lane & 7;               // sub-lane: 8 dims each
    const int dq  = hh * HD + sl * 8;       // this lane's 8 dims (score phase)

    // loop-invariant q slice: 8 halfs = 1 uint4 (broadcast smem read)
    const uint4 qv = *(const uint4*)&q_s[dq];
    const float2 q0 = __half22float2(*(__half2*)&qv.x);
    const float2 q1 = __half22float2(*(__half2*)&qv.y);
    const float2 q2 = __half22float2(*(__half2*)&qv.z);
    const float2 q3 = __half22float2(*(__half2*)&qv.w);

    // ---- scores: 4 neighbors per warp-iteration ----
    float mx = -1e30f;
    for (int j0 = 0; j0 < deg; j0 += 4) {
        int   j = j0 + grp;
        float s = -1e30f;
        if (j < deg) {
            int pk   = nbr_s[j];
            int m    = pk & 0xFFFFF;
            int code = pk >> 20;
            uint4 kv = *(const uint4*)(g_k2h + (size_t)m * FDIM + dq);
            float2 k0 = __half22float2(*(__half2*)&kv.x);
            float2 k1 = __half22float2(*(__half2*)&kv.y);
            float2 k2 = __half22float2(*(__half2*)&kv.z);
            float2 k3 = __half22float2(*(__half2*)&kv.w);
            float pa = fmaf(q0.x, k0.x, q0.y * k0.y);
            pa = fmaf(q1.x, k1.x, pa); pa = fmaf(q1.y, k1.y, pa);
            float pb = fmaf(q2.x, k2.x, q2.y * k2.y);
            pb = fmaf(q3.x, k3.x, pb); pb = fmaf(q3.y, k3.y, pb);
            float part = pa + pb;
            #pragma unroll
            for (int off = 4; off; off >>= 1)
                part += __shfl_xor_sync(0xffffffffu, part, off, 8);
            s = fmaf(part, 0.125f, wsh_s[code]);
            if (sl == 0) sc_s[hh][j] = s;
        } else {
            // keep shuffle participation uniform within the group
            float dummy = 0.f;
            #pragma unroll
            for (int off = 4; off; off >>= 1)
                dummy += __shfl_xor_sync(0xffffffffu, dummy, off, 8);
        }
        mx = fmaxf(mx, s);
    }
    // full-warp max (each lane saw only its group's neighbors)
    #pragma unroll
    for (int off = 16; off; off >>= 1)
        mx = fmaxf(mx, __shfl_xor_sync(0xffffffffu, mx, off));
    __syncwarp();

    // ---- softmax over the list ----
    float sum = 0.f;
    for (int j = lane; j < deg; j += 32) {
        float p = __expf(sc_s[hh][j] - mx);
        sc_s[hh][j] = p;
        sum += p;
    }
    #pragma unroll
    for (int off = 16; off; off >>= 1)
        sum += __shfl_xor_sync(0xffffffffu, sum, off);
    const float inv = 1.f / sum;
    __syncwarp();

    // ---- PV: lanes over dims, serial neighbors (coalesced) ----
    const int dof = hh * HD + lane * 2;
    float o0 = 0.f, o1 = 0.f;
    #pragma unroll 8
    for (int j = 0; j < deg; j++) {
        int   m = nbr_s[j] & 0xFFFFF;
        float p = sc_s[hh][j];
        float2 f = __half22float2(*(const __half2*)(g_v2h + (size_t)m * FDIM + dof));
        o0 = fmaf(p, f.x, o0);
        o1 = fmaf(p, f.y, o1);
    }
    __half2 h;
    h.x = __float2half_rn(o0 * inv);
    h.y = __float2half_rn(o1 * inv);
    *(__half2*)(g_abatt + (size_t)n * KP + dof) = h;
}

// ---------------- launch ----------------
extern "C" void kernel_launch(void* const* d_in, const int* in_sizes, int n_in,
                              void* d_out, int out_size) {
    ProArgs a;
    a.x   = (const float*)d_in[0];
    a.ei  = (const int*)d_in[1];
    a.et  = (const int*)d_in[2];
    const float* etw = (const float*)d_in[3];
    a.wq  = (const float*)d_in[4];   a.bq  = (const float*)d_in[5];
    a.wk  = (const float*)d_in[6];   a.bk  = (const float*)d_in[7];
    a.wv  = (const float*)d_in[8];   a.bv  = (const float*)d_in[9];
    a.wiq = (const float*)d_in[10];  a.biq = (const float*)d_in[11];
    a.wik = (const float*)d_in[12];  a.bik = (const float*)d_in[13];
    a.wiv = (const float*)d_in[14];  a.biv = (const float*)d_in[15];
    a.wo  = (const float*)d_in[16];
    const float* bo = (const float*)d_in[17];
    float* out = (float*)d_out;

    cudaFuncSetAttribute(phase2_kernel,     cudaFuncAttributeMaxDynamicSharedMemorySize, GEMM_SMEM);
    cudaFuncSetAttribute(gemm_main_kernel,  cudaFuncAttributeMaxDynamicSharedMemorySize, GEMM_SMEM);
    cudaFuncSetAttribute(gemm_final_kernel, cudaFuncAttributeMaxDynamicSharedMemorySize, GEMM_SMEM);

    prologue_kernel<<<P1_BLOCKS, 256>>>(a);
    phase2_kernel<<<P2_BLOCKS, 256, GEMM_SMEM>>>();
    gemm_main_kernel<<<dim3(FDIM / 128, NN / 128, 3), 256, GEMM_SMEM>>>();
    attn_sparse_kernel<<<NN, 512>>>(etw);
    gemm_final_kernel<<<dim3(FDIM / 128, NN / 128), 256, GEMM_SMEM>>>(bo, out);
}

// round 17
// speedup vs baseline: 1.4066x; 1.0058x over previous
#include <cuda_runtime.h>
#include <cuda_fp16.h>
#include <math.h>
#include <stdint.h>

#define NN     3072
#define EE     98304
#define FDIM   1024
#define HD     64
#define MAXDEG 256
#define KP     1024          // fp16 GEMM K
#define NTP    (KP / 32)     // 32 BK32 tiles
#define WPSZ   ((size_t)FDIM * KP)

// ---------------- scratch (static device arrays; no allocation) ----------------
__device__ int   g_cnt[NN];                   // zero-init; csr2 resets after use
__device__ int   g_ecol[NN * MAXDEG];
__device__ int   g_eeid[NN * MAXDEG];
__device__ int   g_adj[NN * MAXDEG];
__device__ int   g_deg[NN];
__device__ __half g_q2h[NN * FDIM];           // fp16 q2/k2/v2
__device__ __half g_k2h[NN * FDIM];
__device__ __half g_v2h[NN * FDIM];
__device__ float g_bf[3 * FDIM];              // fused biases
__device__ float g_zb[FDIM];                  // zero bias (static zero-init)
__device__ __half g_ab   [NN * KP];           // fp16 cast of x
__device__ __half g_abatt[NN * KP];           // fp16 cast of attn out
__device__ __half g_wia[3 * WPSZ];            // fp16 cast of Wiq/Wik/Wiv
__device__ __half g_wtb[3 * WPSZ];            // fp16 cast of Wq^T/Wk^T/Wv^T
__device__ __half g_wb [4 * WPSZ];            // fp16: Wf0..2 (from fuse), wo

// ---------------- PTX helpers ----------------
__device__ __forceinline__ uint32_t smem_u32(const void* p) {
    uint32_t a;
    asm("{ .reg .u64 t; cvta.to.shared.u64 t, %1; cvt.u32.u64 %0, t; }" : "=r"(a) : "l"(p));
    return a;
}
__device__ __forceinline__ void cp16(uint32_t dst, const void* src) {
    asm volatile("cp.async.cg.shared.global [%0], [%1], 16;" :: "r"(dst), "l"(src));
}
__device__ __forceinline__ void ldsm4(uint32_t* r, uint32_t a) {
    asm volatile("ldmatrix.sync.aligned.m8n8.x4.shared.b16 {%0,%1,%2,%3}, [%4];"
                 : "=r"(r[0]), "=r"(r[1]), "=r"(r[2]), "=r"(r[3]) : "r"(a));
}
__device__ __forceinline__ void ldsm2(uint32_t* r, uint32_t a) {
    asm volatile("ldmatrix.sync.aligned.m8n8.x2.shared.b16 {%0,%1}, [%2];"
                 : "=r"(r[0]), "=r"(r[1]) : "r"(a));
}
__device__ __forceinline__ void mma16816(float* c, const uint32_t* a, const uint32_t* b) {
    asm volatile(
        "mma.sync.aligned.m16n8k16.row.col.f32.f16.f16.f32 "
        "{%0,%1,%2,%3}, {%4,%5,%6,%7}, {%8,%9}, {%0,%1,%2,%3};"
        : "+f"(c[0]), "+f"(c[1]), "+f"(c[2]), "+f"(c[3])
        : "r"(a[0]), "r"(a[1]), "r"(a[2]), "r"(a[3]), "r"(b[0]), "r"(b[1]));
}

// ---------------- phase 1: all independent prep work in ONE launch ----------------
#define P1_BLOCKS 10636

struct ProArgs {
    const float *x;
    const int   *ei, *et;
    const float *wq, *wk, *wv, *wiq, *wik, *wiv, *wo;
    const float *bq, *bk, *bv, *biq, *bik, *biv;
};

__global__ __launch_bounds__(256) void prologue_kernel(ProArgs a) {
    const int b   = blockIdx.x;
    const int tid = threadIdx.x;

    if (b < 3072) {                                   // ---- conv_wia ----
        const int w  = b >> 10;
        const int i  = (b & 1023) * 256 + tid;
        const float* W = (w == 0) ? a.wiq : (w == 1) ? a.wik : a.wiv;
        float4 v = ((const float4*)W)[i];
        __half2 h01, h23;
        h01.x = __float2half_rn(v.x); h01.y = __float2half_rn(v.y);
        h23.x = __float2half_rn(v.z); h23.y = __float2half_rn(v.w);
        __half* A = g_wia + (size_t)w * WPSZ;
        *(__half2*)(A + i * 4)     = h01;
        *(__half2*)(A + i * 4 + 2) = h23;
    } else if (b < 6144) {                            // ---- conv_wt ----
        const int bb = b - 3072;
        const int w  = bb >> 10;
        const int t2 = bb & 1023;
        const int n0 = (t2 & 31) * 32;
        const int k0 = (t2 >> 5) * 32;
        const float* W = (w == 0) ? a.wq : (w == 1) ? a.wk : a.wv;
        __shared__ float t[32][33];
        const int tx = tid & 31;
        const int ty = tid >> 5;
        #pragma unroll
        for (int r = ty; r < 32; r += 8)
            t[r][tx] = W[(size_t)(k0 + r) * FDIM + n0 + tx];
        __syncthreads();
        __half* B = g_wtb + (size_t)w * WPSZ;
        #pragma unroll
        for (int rr = ty; rr < 32; rr += 8)
            B[(size_t)(n0 + rr) * KP + k0 + tx] = __float2half_rn(t[tx][rr]);
    } else if (b < 7168) {                            // ---- wo cast ----
        const int i = (b - 6144) * 256 + tid;
        float4 v = ((const float4*)a.wo)[i];
        __half2 h01, h23;
        h01.x = __float2half_rn(v.x); h01.y = __float2half_rn(v.y);
        h23.x = __float2half_rn(v.z); h23.y = __float2half_rn(v.w);
        __half* A = g_wb + (size_t)3 * WPSZ;
        *(__half2*)(A + i * 4)     = h01;
        *(__half2*)(A + i * 4 + 2) = h23;
    } else if (b < 10240) {                           // ---- x cast ----
        const int i = (b - 7168) * 256 + tid;
        float4 v = ((const float4*)a.x)[i];
        __half2 h01, h23;
        h01.x = __float2half_rn(v.x); h01.y = __float2half_rn(v.y);
        h23.x = __float2half_rn(v.z); h23.y = __float2half_rn(v.w);
        *(__half2*)(g_ab + i * 4)     = h01;
        *(__half2*)(g_ab + i * 4 + 2) = h23;
    } else if (b < 10624) {                           // ---- edge scatter ----
        const int e = (b - 10240) * 256 + tid;
        int s = a.ei[e], d = a.ei[EE + e];
        int pos = atomicAdd(&g_cnt[s], 1);
        if (pos < MAXDEG) {
            g_ecol[s * MAXDEG + pos] = d | (a.et[e] << 20);
            g_eeid[s * MAXDEG + pos] = e;
        }
    } else {                                          // ---- bias fuse ----
        const int idx = b - 10624;
        const int z   = idx >> 2;
        const int n   = (idx & 3) * 256 + tid;
        const float* W  = ((z == 0) ? a.wiq : (z == 1) ? a.wik : a.wiv) + (size_t)n * FDIM;
        const float* bi = (z == 0) ? a.bq : (z == 1) ? a.bk : a.bv;
        const float* bo = (z == 0) ? a.biq : (z == 1) ? a.bik : a.biv;
        float s = 0.f;
        #pragma unroll 8
        for (int k = 0; k < FDIM; k++) s = fmaf(W[k], bi[k], s);
        g_bf[z * FDIM + n] = s + bo[n];
    }
}

// ---------------- mma.sync fp16 GEMM core ----------------
#define STAGE_BYTES 16384
#define GEMM_SMEM   (3 * STAGE_BYTES)

__device__ __forceinline__ void load_tile_pair(
    const __half* Abase, const __half* Bbase,
    int row0, int col0, int k0, uint32_t sA, uint32_t sB, int tid)
{
    #pragma unroll
    for (int i = 0; i < 2; i++) {
        int c   = tid + i * 256;
        int row = c >> 2;
        int kc  = c & 3;
        uint32_t soff = (uint32_t)(((row >> 3) * 4 + kc) * 128 + (row & 7) * 16);
        cp16(sA + soff, Abase + (size_t)(row0 + row) * KP + k0 + kc * 8);
        cp16(sB + soff, Bbase + (size_t)(col0 + row) * KP + k0 + kc * 8);
    }
}

// MODE 0: fp32 out + bias.  MODE 1: fp16 out + bias.  Row stride FDIM both.
template<int MODE>
__device__ __forceinline__ void gemm_core(
    int bx, int by,
    const __half* __restrict__ A, const __half* __restrict__ B,
    const float* __restrict__ bias, float* __restrict__ Yf,
    __half* __restrict__ Ys)
{
    extern __shared__ char smem[];
    const uint32_t sb = smem_u32(smem);
    const int tid  = threadIdx.x;
    const int wid  = tid >> 5;
    const int lane = tid & 31;
    const int wm   = wid & 1;
    const int wn   = wid >> 1;
    const int row0 = by << 7;
    const int col0 = bx << 7;

    const int g  = lane >> 3;
    const int r8 = lane & 7;
    const uint32_t aconst = (uint32_t)((wm * 8 + (g & 1)) * 512 + (g >> 1) * 128 + r8 * 16);
    const uint32_t bconst = (uint32_t)(wn * 4 * 512 + (g & 1) * 128 + r8 * 16);

    float acc[4][4][4];
    #pragma unroll
    for (int mt = 0; mt < 4; mt++)
        #pragma unroll
        for (int nt = 0; nt < 4; nt++)
            acc[mt][nt][0] = acc[mt][nt][1] = acc[mt][nt][2] = acc[mt][nt][3] = 0.f;

    load_tile_pair(A, B, row0, col0, 0, sb, sb + 8192, tid);
    asm volatile("cp.async.commit_group;" ::: "memory");
    load_tile_pair(A, B, row0, col0, 32, sb + STAGE_BYTES, sb + STAGE_BYTES + 8192, tid);
    asm volatile("cp.async.commit_group;" ::: "memory");

    int buf = 0;
    for (int t = 0; t < NTP; t++) {
        asm volatile("cp.async.wait_group 1;" ::: "memory");
        __syncthreads();

        int nbuf = buf + 1; if (nbuf == 3) nbuf = 0;
        int lbuf = nbuf + 1; if (lbuf == 3) lbuf = 0;
        if (t + 2 < NTP) {
            uint32_t ls = sb + (uint32_t)lbuf * STAGE_BYTES;
            load_tile_pair(A, B, row0, col0, (t + 2) * 32, ls, ls + 8192, tid);
        }
        asm volatile("cp.async.commit_group;" ::: "memory");

        const uint32_t Ab = sb + (uint32_t)buf * STAGE_BYTES;
        const uint32_t Bb = Ab + 8192;
        #pragma unroll
        for (int kt = 0; kt < 2; kt++) {
            uint32_t af[4][4], bfr[4][2];
            #pragma unroll
            for (int mt = 0; mt < 4; mt++)
                ldsm4(af[mt], Ab + aconst + (uint32_t)(mt * 1024 + kt * 256));
            #pragma unroll
            for (int nt = 0; nt < 4; nt++)
                ldsm2(bfr[nt], Bb + bconst + (uint32_t)(nt * 512 + kt * 256));
            #pragma unroll
            for (int mt = 0; mt < 4; mt++)
                #pragma unroll
                for (int nt = 0; nt < 4; nt++)
                    mma16816(acc[mt][nt], af[mt], bfr[nt]);
        }
        buf = nbuf;
    }

    const int mbase = row0 + wm * 64 + (lane >> 2);
    const int nbase = col0 + wn * 32 + (lane & 3) * 2;
    #pragma unroll
    for (int mt = 0; mt < 4; mt++) {
        #pragma unroll
        for (int nt = 0; nt < 4; nt++) {
            int m = mbase + mt * 16;
            int n = nbase + nt * 8;
            float2 b2 = *(const float2*)&bias[n];
            float y0 = acc[mt][nt][0] + b2.x, y1 = acc[mt][nt][1] + b2.y;
            float y2 = acc[mt][nt][2] + b2.x, y3 = acc[mt][nt][3] + b2.y;
            if (MODE == 0) {
                *(float2*)&Yf[(size_t)m * FDIM + n]       = make_float2(y0, y1);
                *(float2*)&Yf[(size_t)(m + 8) * FDIM + n] = make_float2(y2, y3);
            } else {
                __half2 h0, h1;
                h0.x = __float2half_rn(y0); h0.y = __float2half_rn(y1);
                h1.x = __float2half_rn(y2); h1.y = __float2half_rn(y3);
                *(__half2*)(Ys + (size_t)m * FDIM + n)       = h0;
                *(__half2*)(Ys + (size_t)(m + 8) * FDIM + n) = h1;
            }
        }
    }
}

// ---------------- phase 2: fuse GEMM (blocks 0..191) + csr dedup (192..3263) ----------------
#define P2_BLOCKS (192 + NN)

__global__ __launch_bounds__(256) void phase2_kernel() {
    if (blockIdx.x < 192) {
        const int b  = blockIdx.x;
        const int z  = b >> 6;
        const int bb = b & 63;
        gemm_core<1>(bb & 7, bb >> 3,
                     g_wia + (size_t)z * WPSZ, g_wtb + (size_t)z * WPSZ,
                     g_zb, nullptr, g_wb + (size_t)z * WPSZ);
        return;
    }
    const int n   = blockIdx.x - 192;
    const int tid = threadIdx.x;
    __shared__ int scol[MAXDEG], seid[MAXDEG];
    __shared__ int outc, sflag;
    if (tid == 0) { outc = 0; sflag = 0; }
    int cnt = g_cnt[n];
    if (cnt > MAXDEG) cnt = MAXDEG;
    if (tid < cnt) {
        scol[tid] = g_ecol[n * MAXDEG + tid];
        seid[tid] = g_eeid[n * MAXDEG + tid];
    }
    __syncthreads();
    if (tid < cnt) {
        int cj = scol[tid] & 0xFFFFF;
        int ej = seid[tid];
        bool win = true;
        for (int i = 0; i < cnt; i++)
            if ((scol[i] & 0xFFFFF) == cj && seid[i] > ej) { win = false; break; }
        if (win) {
            int pos = atomicAdd(&outc, 1);
            g_adj[n * MAXDEG + pos] = scol[tid];
            if (cj == n) sflag = 1;
        }
    }
    __syncthreads();
    if (tid == 0) {
        int d = outc;
        if (!sflag && d < MAXDEG) { g_adj[n * MAXDEG + d] = n | (4 << 20); d++; }
        g_deg[n] = d;
        g_cnt[n] = 0;           // reset for next graph replay (deterministic)
    }
}

// ---------------- phase 3: q2/k2/v2 (all fp16 out) ----------------
__global__ __launch_bounds__(256) void gemm_main_kernel() {
    const int z = blockIdx.z;
    __half* Ys = (z == 0) ? g_q2h : (z == 1) ? g_k2h : g_v2h;
    gemm_core<1>(blockIdx.x, blockIdx.y, g_ab, g_wb + (size_t)z * WPSZ,
                 g_bf + z * FDIM, nullptr, Ys);
}

// ---------------- phase 5: out = fl16(att) @ wo + bo ----------------
__global__ __launch_bounds__(256) void gemm_final_kernel(const float* bias, float* Y) {
    gemm_core<0>(blockIdx.x, blockIdx.y, g_abatt, g_wb + (size_t)3 * WPSZ, bias, Y, nullptr);
}

// ---------------- phase 4: sparse gather attention ----------------
// Score phase: 4 groups of 8 lanes, one neighbor/group (8 dims/lane), packed
// HFMA2 partial dot (4 instr vs 16), width-8 butterfly. PV: fp32, coalesced.
__global__ __launch_bounds__(512, 2) void attn_sparse_kernel(const float* __restrict__ etw)
{
    __shared__ __half q_s[FDIM];           // 2 KB
    __shared__ int    nbr_s[MAXDEG];
    __shared__ float  sc_s[16][MAXDEG];    // 16 KB
    __shared__ float  wsh_s[8];

    const int n    = blockIdx.x;
    const int tid  = threadIdx.x;
    const int hh   = tid >> 5;
    const int lane = tid & 31;

    if (tid < 4) wsh_s[tid + 1] = log1pf(expf(etw[tid]));
    ((uint32_t*)q_s)[tid] = ((const uint32_t*)(g_q2h + (size_t)n * FDIM))[tid];
    const int deg = g_deg[n];
    for (int j = tid; j < deg; j += 512) nbr_s[j] = g_adj[n * MAXDEG + j];
    __syncthreads();

    const int grp = lane >> 3;              // neighbor group 0..3
    const int sl  = lane & 7;               // sub-lane: 8 dims each
    const int dq  = hh * HD + sl * 8;       // this lane's 8 dims (score phase)

    // loop-invariant q slice: 8 halfs = 4 half2 (broadcast smem read)
    const uint4 qv = *(const uint4*)&q_s[dq];
    const __half2 q0 = *(const __half2*)&qv.x;
    const __half2 q1 = *(const __half2*)&qv.y;
    const __half2 q2 = *(const __half2*)&qv.z;
    const __half2 q3 = *(const __half2*)&qv.w;

    // ---- scores: 4 neighbors per warp-iteration, packed HFMA2 dot ----
    float mx = -1e30f;
    for (int j0 = 0; j0 < deg; j0 += 4) {
        int   j = j0 + grp;
        float s = -1e30f;
        if (j < deg) {
            int pk   = nbr_s[j];
            int m    = pk & 0xFFFFF;
            int code = pk >> 20;
            uint4 kv = *(const uint4*)(g_k2h + (size_t)m * FDIM + dq);
            __half2 acc = __hmul2(q0, *(const __half2*)&kv.x);
            acc = __hfma2(q1, *(const __half2*)&kv.y, acc);
            acc = __hfma2(q2, *(const __half2*)&kv.z, acc);
            acc = __hfma2(q3, *(const __half2*)&kv.w, acc);
            float2 pf = __half22float2(acc);
            float part = pf.x + pf.y;
            #pragma unroll
            for (int off = 4; off; off >>= 1)
                part += __shfl_xor_sync(0xffffffffu, part, off, 8);
            s = fmaf(part, 0.125f, wsh_s[code]);
            if (sl == 0) sc_s[hh][j] = s;
        } else {
            // keep shuffle participation uniform within the group
            float dummy = 0.f;
            #pragma unroll
            for (int off = 4; off; off >>= 1)
                dummy += __shfl_xor_sync(0xffffffffu, dummy, off, 8);
        }
        mx = fmaxf(mx, s);
    }
    // full-warp max (each lane saw only its group's neighbors)
    #pragma unroll
    for (int off = 16; off; off >>= 1)
        mx = fmaxf(mx, __shfl_xor_sync(0xffffffffu, mx, off));
    __syncwarp();

    // ---- softmax over the list ----
    float sum = 0.f;
    for (int j = lane; j < deg; j += 32) {
        float p = __expf(sc_s[hh][j] - mx);
        sc_s[hh][j] = p;
        sum += p;
    }
    #pragma unroll
    for (int off = 16; off; off >>= 1)
        sum += __shfl_xor_sync(0xffffffffu, sum, off);
    const float inv = 1.f / sum;
    __syncwarp();

    // ---- PV: lanes over dims, serial neighbors (coalesced, fp32) ----
    const int dof = hh * HD + lane * 2;
    float o0 = 0.f, o1 = 0.f;
    #pragma unroll 8
    for (int j = 0; j < deg; j++) {
        int   m = nbr_s[j] & 0xFFFFF;
        float p = sc_s[hh][j];
        float2 f = __half22float2(*(const __half2*)(g_v2h + (size_t)m * FDIM + dof));
        o0 = fmaf(p, f.x, o0);
        o1 = fmaf(p, f.y, o1);
    }
    __half2 h;
    h.x = __float2half_rn(o0 * inv);
    h.y = __float2half_rn(o1 * inv);
    *(__half2*)(g_abatt + (size_t)n * KP + dof) = h;
}

// ---------------- launch ----------------
extern "C" void kernel_launch(void* const* d_in, const int* in_sizes, int n_in,
                              void* d_out, int out_size) {
    ProArgs a;
    a.x   = (const float*)d_in[0];
    a.ei  = (const int*)d_in[1];
    a.et  = (const int*)d_in[2];
    const float* etw = (const float*)d_in[3];
    a.wq  = (const float*)d_in[4];   a.bq  = (const float*)d_in[5];
    a.wk  = (const float*)d_in[6];   a.bk  = (const float*)d_in[7];
    a.wv  = (const float*)d_in[8];   a.bv  = (const float*)d_in[9];
    a.wiq = (const float*)d_in[10];  a.biq = (const float*)d_in[11];
    a.wik = (const float*)d_in[12];  a.bik = (const float*)d_in[13];
    a.wiv = (const float*)d_in[14];  a.biv = (const float*)d_in[15];
    a.wo  = (const float*)d_in[16];
    const float* bo = (const float*)d_in[17];
    float* out = (float*)d_out;

    cudaFuncSetAttribute(phase2_kernel,     cudaFuncAttributeMaxDynamicSharedMemorySize, GEMM_SMEM);
    cudaFuncSetAttribute(gemm_main_kernel,  cudaFuncAttributeMaxDynamicSharedMemorySize, GEMM_SMEM);
    cudaFuncSetAttribute(gemm_final_kernel, cudaFuncAttributeMaxDynamicSharedMemorySize, GEMM_SMEM);

    prologue_kernel<<<P1_BLOCKS, 256>>>(a);
    phase2_kernel<<<P2_BLOCKS, 256, GEMM_SMEM>>>();
    gemm_main_kernel<<<dim3(FDIM / 128, NN / 128, 3), 256, GEMM_SMEM>>>();
    attn_sparse_kernel<<<NN, 512>>>(etw);
    gemm_final_kernel<<<dim3(FDIM / 128, NN / 128), 256, GEMM_SMEM>>>(bo, out);
}